// round 1
// baseline (speedup 1.0000x reference)
#include <cuda_runtime.h>

#define B_  8
#define N_  8192
#define H_  256
#define KD_ 260            // H + 4 (h | s_l(3) | score)
#define NU_ (N_/4)         // 2048
#define ND_ (N_-NU_)       // 6144
#define M_  5

// ---------------- device scratch (no allocations allowed) ----------------
__device__ int g_up_idx[B_*NU_];     // up nodes, ascending, local node id
__device__ int g_down_idx[B_*ND_];   // down nodes, ascending, local node id
__device__ int g_dst[B_*ND_*M_];     // per down node: 5 global up-node indices

// order-preserving float <-> uint encode (unsigned compare == float compare)
__device__ __forceinline__ unsigned enc_f(float f){
    unsigned u = __float_as_uint(f);
    return (u & 0x80000000u) ? ~u : (u | 0x80000000u);
}
__device__ __forceinline__ float dec_f(unsigned k){
    unsigned u = (k & 0x80000000u) ? (k ^ 0x80000000u) : ~k;
    return __uint_as_float(u);
}

// block-wide exclusive scan over 1024 per-thread values (Hillis-Steele)
__device__ __forceinline__ int block_scan_excl(int val, int* s_part, int tid){
    s_part[tid] = val;
    __syncthreads();
    for (int off = 1; off < 1024; off <<= 1){
        int v = (tid >= off) ? s_part[tid - off] : 0;
        __syncthreads();
        s_part[tid] += v;
        __syncthreads();
    }
    return s_part[tid] - val;   // exclusive
}

// ------------------- K1: top-25% selection + compaction -------------------
// Exact jax semantics: argsort(-scores) stable -> on equal score, lower index
// ranks first. We radix-select the threshold score-encoding T, then among
// enc==T take the (n_up - count_gt) lowest indices.
__global__ void k_select(const float* __restrict__ scores,
                         float* __restrict__ d_out, long long out_size){
    __shared__ unsigned s_enc[N_];
    __shared__ int s_part[1024];
    __shared__ int s_hist[16];
    __shared__ int s_bcast[2];
    const int b = blockIdx.x, tid = threadIdx.x;
    const float* sc = scores + (long long)b * N_;
    for (int i = tid; i < N_; i += 1024) s_enc[i] = enc_f(sc[i]);
    __syncthreads();

    // MSD radix select (4 bits / level) for the NU_-th largest encoding
    unsigned prefix = 0, known = 0;
    int k = NU_;
    for (int lvl = 7; lvl >= 0; --lvl){
        if (tid < 16) s_hist[tid] = 0;
        __syncthreads();
        const int sh = lvl * 4;
        for (int i = tid; i < N_; i += 1024){
            unsigned e = s_enc[i];
            if ((e & known) == prefix) atomicAdd(&s_hist[(e >> sh) & 15], 1);
        }
        __syncthreads();
        if (tid == 0){
            int kk = k, bin = 15;
            while (bin > 0 && kk > s_hist[bin]) { kk -= s_hist[bin]; --bin; }
            s_bcast[0] = bin; s_bcast[1] = kk;
        }
        __syncthreads();
        prefix |= ((unsigned)s_bcast[0]) << sh;
        known  |= 0xFu << sh;
        k = s_bcast[1];
        __syncthreads();
    }
    const unsigned T = prefix;

    // count strictly greater than T
    if (tid == 0) s_bcast[0] = 0;
    __syncthreads();
    {
        int loc = 0;
        for (int i = tid; i < N_; i += 1024) if (s_enc[i] > T) loc++;
        atomicAdd(&s_bcast[0], loc);
    }
    __syncthreads();
    const int need_eq = NU_ - s_bcast[0];
    __syncthreads();

    // scan A: rank (index-ascending) among enc==T
    const int base = tid * 8;
    int eqc = 0;
#pragma unroll
    for (int e = 0; e < 8; ++e) eqc += (s_enc[base + e] == T);
    int eqbase = block_scan_excl(eqc, s_part, tid);

    // per-element masks
    unsigned mbits = 0; int upc = 0;
    {
        int ec = eqbase;
#pragma unroll
        for (int e = 0; e < 8; ++e){
            unsigned v = s_enc[base + e];
            bool msk;
            if (v > T) msk = true;
            else if (v == T) { msk = (ec < need_eq); ec++; }
            else msk = false;
            if (msk) { mbits |= (1u << e); upc++; }
        }
    }
    __syncthreads();
    int upbase = block_scan_excl(upc, s_part, tid);

    // compaction + (optional) mask tail of output
    const long long BNH = (long long)B_ * N_ * H_;
    const bool wf = (out_size == BNH + (long long)B_ * N_);        // mask as f32
    const bool wb = (out_size == BNH + ((long long)B_ * N_) / 4);  // mask as bytes
    int up = upbase;
#pragma unroll
    for (int e = 0; e < 8; ++e){
        const int i = base + e;
        const bool msk = (mbits >> e) & 1;
        if (msk) { g_up_idx[b * NU_ + up] = i; up++; }
        else       g_down_idx[b * ND_ + (i - up)] = i;
        if (wf)      d_out[BNH + (long long)b * N_ + i] = msk ? 1.0f : 0.0f;
        else if (wb) ((unsigned char*)d_out)[BNH * 4 + (long long)b * N_ + i] = msk ? 1 : 0;
    }
}

// ------------------------- K2: directional 5-NN ---------------------------
__global__ void k_knn(const float* __restrict__ s_l){
    __shared__ float sx[NU_], sy[NU_], sz[NU_];
    __shared__ int   sui[NU_];
    const int b = blockIdx.y;
    const int tid = threadIdx.x;
    for (int j = tid; j < NU_; j += 256){
        int u = g_up_idx[b * NU_ + j];
        long long p = ((long long)b * N_ + u) * 3;
        sx[j] = s_l[p]; sy[j] = s_l[p + 1]; sz[j] = s_l[p + 2];
        sui[j] = b * N_ + u;
    }
    __syncthreads();
    const int dl = blockIdx.x * 256 + tid;
    if (dl >= ND_) return;
    const int dn = g_down_idx[b * ND_ + dl];
    long long p = ((long long)b * N_ + dn) * 3;
    const float x = s_l[p], y = s_l[p + 1], z = s_l[p + 2];

    const float INF = __int_as_float(0x7f800000);
    float b0 = INF, b1 = INF, b2 = INF, b3 = INF, b4 = INF;
    int   i0 = 0,  i1 = 0,  i2 = 0,  i3 = 0,  i4 = 0;
    // strict '<' insertion keeps lower index first on ties (== lax.top_k)
    for (int j = 0; j < NU_; ++j){
        float dx = x - sx[j], dy = y - sy[j], dz = z - sz[j];
        float d = dx * dx + dy * dy + dz * dz;
        if (d < b4){
            if (d < b3){ b4 = b3; i4 = i3;
                if (d < b2){ b3 = b2; i3 = i2;
                    if (d < b1){ b2 = b1; i2 = i1;
                        if (d < b0){ b1 = b0; i1 = i0; b0 = d; i0 = j; }
                        else       { b1 = d;  i1 = j; }
                    } else { b2 = d; i2 = j; }
                } else { b3 = d; i3 = j; }
            } else { b4 = d; i4 = j; }
        }
    }
    int* dst = g_dst + ((long long)b * ND_ + dl) * M_;
    dst[0] = sui[i0]; dst[1] = sui[i1]; dst[2] = sui[i2];
    dst[3] = sui[i3]; dst[4] = sui[i4];
}

// -------------- K3: fused down-row GEMM + encoded scatter-max -------------
// feat[d,:] = [h[d] | s_l[d] | score[d]] @ W + b, scattered as atomicMax(u32)
// into the 5 up destinations of each down row. Only down rows are computed.
__global__ void __launch_bounds__(256, 2)
k_gemm(const float* __restrict__ hh, const float* __restrict__ s_l,
       const float* __restrict__ scores, const float* __restrict__ W,
       const float* __restrict__ bias, unsigned* __restrict__ ok){
    __shared__ float Xs[32][68];    // [k][row], padded vs bank conflicts
    __shared__ float Ws[32][256];   // [k][n]
    __shared__ int   s_g[64];       // global node index per tile row

    const int b  = blockIdx.y;
    const int m0 = blockIdx.x * 64;
    const int tid = threadIdx.x;
    const int tr = tid >> 5, tc = tid & 31;

    if (tid < 64){
        int dn = g_down_idx[b * ND_ + m0 + tid];
        s_g[tid] = b * N_ + dn;
    }
    __syncthreads();

    float acc[8][8];
#pragma unroll
    for (int i = 0; i < 8; ++i)
#pragma unroll
        for (int j = 0; j < 8; ++j) acc[i][j] = 0.0f;

    for (int k0 = 0; k0 < KD_; k0 += 32){
        // X tile: thread loads col (k0+tc) of 8 strided rows (coalesced in k)
        const int kg = k0 + tc;
#pragma unroll
        for (int r = 0; r < 8; ++r){
            const int row = tr + r * 8;
            const int g = s_g[row];
            float v;
            if      (kg < H_)      v = hh[(long long)g * H_ + kg];
            else if (kg < H_ + 3)  v = s_l[(long long)g * 3 + (kg - H_)];
            else if (kg == H_ + 3) v = scores[g];
            else                   v = 0.0f;
            Xs[tc][row] = v;
        }
        // W tile: 32x256, fully coalesced
#pragma unroll
        for (int t = 0; t < 32; ++t){
            const int idx = tid + t * 256;
            const int kw = idx >> 8, n = idx & 255;
            const int kgw = k0 + kw;
            Ws[kw][n] = (kgw < KD_) ? W[(long long)kgw * H_ + n] : 0.0f;
        }
        __syncthreads();

#pragma unroll
        for (int kk = 0; kk < 32; ++kk){
            float4 a0 = *(const float4*)&Xs[kk][tr * 8];
            float4 a1 = *(const float4*)&Xs[kk][tr * 8 + 4];
            float4 c0 = *(const float4*)&Ws[kk][tc * 8];
            float4 c1 = *(const float4*)&Ws[kk][tc * 8 + 4];
            float av[8] = {a0.x, a0.y, a0.z, a0.w, a1.x, a1.y, a1.z, a1.w};
            float bv[8] = {c0.x, c0.y, c0.z, c0.w, c1.x, c1.y, c1.z, c1.w};
#pragma unroll
            for (int ri = 0; ri < 8; ++ri)
#pragma unroll
                for (int ci = 0; ci < 8; ++ci)
                    acc[ri][ci] = fmaf(av[ri], bv[ci], acc[ri][ci]);
        }
        __syncthreads();
    }

    // epilogue: bias + encode + scatter-max to 5 destinations
    float bvv[8];
#pragma unroll
    for (int ci = 0; ci < 8; ++ci) bvv[ci] = bias[tc * 8 + ci];

#pragma unroll
    for (int ri = 0; ri < 8; ++ri){
        const int dl = m0 + tr * 8 + ri;
        const int* ds = &g_dst[((long long)b * ND_ + dl) * M_];
        const int e0 = ds[0], e1 = ds[1], e2 = ds[2], e3 = ds[3], e4 = ds[4];
#pragma unroll
        for (int ci = 0; ci < 8; ++ci){
            const unsigned key = enc_f(acc[ri][ci] + bvv[ci]);
            const int col = tc * 8 + ci;
            atomicMax(&ok[(long long)e0 * H_ + col], key);
            atomicMax(&ok[(long long)e1 * H_ + col], key);
            atomicMax(&ok[(long long)e2 * H_ + col], key);
            atomicMax(&ok[(long long)e3 * H_ + col], key);
            atomicMax(&ok[(long long)e4 * H_ + col], key);
        }
    }
}

// ------------------ K4: in-place decode (0 == "no message") ----------------
__global__ void k_decode(unsigned* __restrict__ ok){
    const long long i = (long long)blockIdx.x * blockDim.x + threadIdx.x;
    uint4 v = ((const uint4*)ok)[i];
    float4 f;
    f.x = v.x ? dec_f(v.x) : 0.0f;
    f.y = v.y ? dec_f(v.y) : 0.0f;
    f.z = v.z ? dec_f(v.z) : 0.0f;
    f.w = v.w ? dec_f(v.w) : 0.0f;
    ((float4*)ok)[i] = f;
}

// ------------------------------- launch ------------------------------------
extern "C" void kernel_launch(void* const* d_in, const int* in_sizes, int n_in,
                              void* d_out, int out_size){
    const float* hh = (const float*)d_in[0];   // h      [B,N,H]
    const float* sl = (const float*)d_in[1];   // s_l    [B,N,3]
    const float* sc = (const float*)d_in[2];   // scores [B,N]
    const float* W  = (const float*)d_in[3];   // W_emb  [H+4,H]
    const float* bb = (const float*)d_in[4];   // b_emb  [H]
    (void)in_sizes; (void)n_in;

    k_select<<<B_, 1024>>>(sc, (float*)d_out, (long long)out_size);

    dim3 gknn(ND_ / 256, B_);
    k_knn<<<gknn, 256>>>(sl);

    cudaMemsetAsync(d_out, 0, (size_t)B_ * N_ * H_ * sizeof(float), 0);

    dim3 gg(ND_ / 64, B_);
    k_gemm<<<gg, 256>>>(hh, sl, sc, W, bb, (unsigned*)d_out);

    const long long nvec = (long long)B_ * N_ * H_ / 4;
    k_decode<<<(unsigned)((nvec + 255) / 256), 256>>>((unsigned*)d_out);
}

// round 3
// speedup vs baseline: 1.3656x; 1.3656x over previous
#include <cuda_runtime.h>
#include <cuda_bf16.h>
#include <mma.h>
#include <cstdint>

using namespace nvcuda;

#define B_  8
#define N_  8192
#define H_  256
#define KD_ 260            // H + 4
#define KP_ 288            // K padded to 9*32
#define NU_ 2048
#define ND_ 6144
#define M_  5
#define BM_ 128            // GEMM M tile
#define BN_ 128            // GEMM N tile
#define BK_ 32             // GEMM K tile
#define LDA 40             // smem A leading dim (pad)
#define LDB 136            // smem B leading dim (pad)

// ---------------- device scratch ----------------
__device__ int  g_up_idx[B_*NU_];
__device__ int  g_down_idx[B_*ND_];
__device__ int  g_dst[B_*ND_*M_];          // per edge: global up node id
__device__ unsigned char g_isup[B_*N_];
__device__ int  g_deg[B_*N_];
__device__ int  g_off[B_*N_];
__device__ int  g_cur[B_*N_];
__device__ int  g_src[B_*ND_*M_];          // CSR payload: down slot (b*ND+dl)
__device__ float g_feat[(size_t)B_*ND_*H_];           // 50 MB feature buffer
__device__ __nv_bfloat16 g_Whi[KP_*H_];
__device__ __nv_bfloat16 g_Wlo[KP_*H_];

__device__ __forceinline__ unsigned enc_f(float f){
    unsigned u = __float_as_uint(f);
    return (u & 0x80000000u) ? ~u : (u | 0x80000000u);
}

__device__ __forceinline__ int block_scan_excl(int val, int* s_part, int tid){
    s_part[tid] = val;
    __syncthreads();
    for (int off = 1; off < 1024; off <<= 1){
        int v = (tid >= off) ? s_part[tid - off] : 0;
        __syncthreads();
        s_part[tid] += v;
        __syncthreads();
    }
    return s_part[tid] - val;
}

// ---------------- K0: W split into hi/lo bf16 (row-major, K padded) --------
__global__ void k_wsplit(const float* __restrict__ W){
    const int idx = blockIdx.x * 256 + threadIdx.x;   // KP_*H_ = 73728
    if (idx >= KP_ * H_) return;
    const int k = idx / H_, n = idx % H_;
    const float w = (k < KD_) ? W[k * H_ + n] : 0.0f;
    const __nv_bfloat16 hi = __float2bfloat16(w);
    const __nv_bfloat16 lo = __float2bfloat16(w - __bfloat162float(hi));
    g_Whi[idx] = hi;
    g_Wlo[idx] = lo;
}

// ---------------- K1: top-25% selection + compaction ----------------
__global__ void k_select(const float* __restrict__ scores,
                         float* __restrict__ d_out, long long out_size){
    __shared__ unsigned s_enc[N_];
    __shared__ int s_part[1024];
    __shared__ int s_hist[16];
    __shared__ int s_bcast[2];
    const int b = blockIdx.x, tid = threadIdx.x;

    for (int i = tid; i < N_; i += 1024) g_deg[b * N_ + i] = 0;

    const float* sc = scores + (long long)b * N_;
    for (int i = tid; i < N_; i += 1024) s_enc[i] = enc_f(sc[i]);
    __syncthreads();

    unsigned prefix = 0, known = 0;
    int k = NU_;
    for (int lvl = 7; lvl >= 0; --lvl){
        if (tid < 16) s_hist[tid] = 0;
        __syncthreads();
        const int sh = lvl * 4;
        for (int i = tid; i < N_; i += 1024){
            unsigned e = s_enc[i];
            if ((e & known) == prefix) atomicAdd(&s_hist[(e >> sh) & 15], 1);
        }
        __syncthreads();
        if (tid == 0){
            int kk = k, bin = 15;
            while (bin > 0 && kk > s_hist[bin]) { kk -= s_hist[bin]; --bin; }
            s_bcast[0] = bin; s_bcast[1] = kk;
        }
        __syncthreads();
        prefix |= ((unsigned)s_bcast[0]) << sh;
        known  |= 0xFu << sh;
        k = s_bcast[1];
        __syncthreads();
    }
    const unsigned T = prefix;

    if (tid == 0) s_bcast[0] = 0;
    __syncthreads();
    {
        int loc = 0;
        for (int i = tid; i < N_; i += 1024) if (s_enc[i] > T) loc++;
        atomicAdd(&s_bcast[0], loc);
    }
    __syncthreads();
    const int need_eq = NU_ - s_bcast[0];
    __syncthreads();

    const int base = tid * 8;
    int eqc = 0;
#pragma unroll
    for (int e = 0; e < 8; ++e) eqc += (s_enc[base + e] == T);
    int eqbase = block_scan_excl(eqc, s_part, tid);

    unsigned mbits = 0; int upc = 0;
    {
        int ec = eqbase;
#pragma unroll
        for (int e = 0; e < 8; ++e){
            unsigned v = s_enc[base + e];
            bool msk;
            if (v > T) msk = true;
            else if (v == T) { msk = (ec < need_eq); ec++; }
            else msk = false;
            if (msk) { mbits |= (1u << e); upc++; }
        }
    }
    __syncthreads();
    int upbase = block_scan_excl(upc, s_part, tid);

    const long long BNH = (long long)B_ * N_ * H_;
    const bool wf = (out_size == BNH + (long long)B_ * N_);
    const bool wb = (out_size == BNH + ((long long)B_ * N_) / 4);
    int up = upbase;
#pragma unroll
    for (int e = 0; e < 8; ++e){
        const int i = base + e;
        const bool msk = (mbits >> e) & 1;
        if (msk) { g_up_idx[b * NU_ + up] = i; up++; }
        else       g_down_idx[b * ND_ + (i - up)] = i;
        g_isup[b * N_ + i] = msk ? 1 : 0;
        if (wf)      d_out[BNH + (long long)b * N_ + i] = msk ? 1.0f : 0.0f;
        else if (wb) ((unsigned char*)d_out)[BNH * 4 + (long long)b * N_ + i] = msk ? 1 : 0;
    }
}

// ---------------- K2: directional 5-NN + degree count ----------------
__global__ void k_knn(const float* __restrict__ s_l){
    __shared__ float sx[NU_], sy[NU_], sz[NU_];
    __shared__ int   sui[NU_];
    const int b = blockIdx.y;
    const int tid = threadIdx.x;
    for (int j = tid; j < NU_; j += 256){
        int u = g_up_idx[b * NU_ + j];
        long long p = ((long long)b * N_ + u) * 3;
        sx[j] = s_l[p]; sy[j] = s_l[p + 1]; sz[j] = s_l[p + 2];
        sui[j] = b * N_ + u;
    }
    __syncthreads();
    const int dl = blockIdx.x * 256 + tid;
    const int dn = g_down_idx[b * ND_ + dl];
    long long p = ((long long)b * N_ + dn) * 3;
    const float x = s_l[p], y = s_l[p + 1], z = s_l[p + 2];

    const float INF = __int_as_float(0x7f800000);
    float b0 = INF, b1 = INF, b2 = INF, b3 = INF, b4 = INF;
    int   i0 = 0,  i1 = 0,  i2 = 0,  i3 = 0,  i4 = 0;
    for (int j = 0; j < NU_; ++j){
        float dx = x - sx[j], dy = y - sy[j], dz = z - sz[j];
        float d = dx * dx + dy * dy + dz * dz;
        if (d < b4){
            if (d < b3){ b4 = b3; i4 = i3;
                if (d < b2){ b3 = b2; i3 = i2;
                    if (d < b1){ b2 = b1; i2 = i1;
                        if (d < b0){ b1 = b0; i1 = i0; b0 = d; i0 = j; }
                        else       { b1 = d;  i1 = j; }
                    } else { b2 = d; i2 = j; }
                } else { b3 = d; i3 = j; }
            } else { b4 = d; i4 = j; }
        }
    }
    int* dst = g_dst + ((long long)b * ND_ + dl) * M_;
    int e0 = sui[i0], e1 = sui[i1], e2 = sui[i2], e3 = sui[i3], e4 = sui[i4];
    dst[0] = e0; dst[1] = e1; dst[2] = e2; dst[3] = e3; dst[4] = e4;
    atomicAdd(&g_deg[e0], 1); atomicAdd(&g_deg[e1], 1); atomicAdd(&g_deg[e2], 1);
    atomicAdd(&g_deg[e3], 1); atomicAdd(&g_deg[e4], 1);
}

// ---------------- K3: exclusive scan of degrees (single block) ----------------
__global__ void k_scan(){
    __shared__ int sp[1024];
    const int tid = threadIdx.x;
    const int base = tid * 64;
    int s = 0;
    for (int i = 0; i < 64; ++i) s += g_deg[base + i];
    int run = block_scan_excl(s, sp, tid);
    for (int i = 0; i < 64; ++i){
        int d = g_deg[base + i];
        g_off[base + i] = run;
        g_cur[base + i] = run;
        run += d;
    }
}

// ---------------- K4: CSR fill ----------------
__global__ void k_fill(){
    const int e = blockIdx.x * 256 + threadIdx.x;
    if (e >= B_ * ND_ * M_) return;
    const int dst = g_dst[e];
    const int pos = atomicAdd(&g_cur[dst], 1);
    g_src[pos] = e / M_;
}

// -------- K5: WMMA bf16 hi/lo GEMM: g_feat[down rows] = X @ W (no bias) ----
__global__ void __launch_bounds__(256)
k_gemm_tc(const float* __restrict__ hh, const float* __restrict__ sl,
          const float* __restrict__ sc){
    __shared__ __nv_bfloat16 Ahi[BM_ * LDA];
    __shared__ __nv_bfloat16 Alo[BM_ * LDA];
    __shared__ __nv_bfloat16 Bhi[BK_ * LDB];
    __shared__ __nv_bfloat16 Blo[BK_ * LDB];
    __shared__ int s_g[BM_];

    const int b   = blockIdx.z;
    const int m0  = blockIdx.x * BM_;
    const int n0  = blockIdx.y * BN_;
    const int tid = threadIdx.x;
    const int w   = tid >> 5;
    const int wm  = w >> 1;          // 0..3  -> warp M offset wm*32
    const int wn  = w & 1;           // 0..1  -> warp N offset wn*64

    if (tid < BM_) s_g[tid] = b * N_ + g_down_idx[b * ND_ + m0 + tid];
    __syncthreads();

    wmma::fragment<wmma::accumulator, 16, 16, 16, float> acc[2][4];
#pragma unroll
    for (int i = 0; i < 2; ++i)
#pragma unroll
        for (int j = 0; j < 4; ++j) wmma::fill_fragment(acc[i][j], 0.0f);

    // A-load mapping: thread -> (row, half of 16 k-elems)
    const int ar  = tid >> 1;
    const int ah  = (tid & 1) * 16;
    const int g   = s_g[ar];
    // B-load mapping: thread -> (k row, 16 n-elems)
    const int bk  = tid >> 3;
    const int bn  = (tid & 7) * 16;

    for (int c = 0; c < KP_ / BK_; ++c){
        const int k0 = c * BK_;
        // ---- A tile: gather + fp32->hi/lo bf16 ----
        float xs[16];
        if (c < 8){
            const float4* hp = (const float4*)(hh + (size_t)g * H_ + k0 + ah);
#pragma unroll
            for (int q = 0; q < 4; ++q){
                float4 f = hp[q];
                xs[4*q] = f.x; xs[4*q+1] = f.y; xs[4*q+2] = f.z; xs[4*q+3] = f.w;
            }
        } else {
#pragma unroll
            for (int q = 0; q < 16; ++q) xs[q] = 0.0f;
            if (ah == 0){
                xs[0] = sl[(size_t)g * 3];
                xs[1] = sl[(size_t)g * 3 + 1];
                xs[2] = sl[(size_t)g * 3 + 2];
                xs[3] = sc[g];
            }
        }
        unsigned hw[8], lw[8];
#pragma unroll
        for (int q = 0; q < 8; ++q){
            __nv_bfloat16 h0 = __float2bfloat16(xs[2*q]);
            __nv_bfloat16 h1 = __float2bfloat16(xs[2*q+1]);
            __nv_bfloat16 l0 = __float2bfloat16(xs[2*q]   - __bfloat162float(h0));
            __nv_bfloat16 l1 = __float2bfloat16(xs[2*q+1] - __bfloat162float(h1));
            __nv_bfloat162 hp2 = __nv_bfloat162(h0, h1);
            __nv_bfloat162 lp2 = __nv_bfloat162(l0, l1);
            hw[q] = *(unsigned*)&hp2;
            lw[q] = *(unsigned*)&lp2;
        }
        {
            uint4* dh = (uint4*)(Ahi + ar * LDA + ah);
            uint4* dl = (uint4*)(Alo + ar * LDA + ah);
            dh[0] = make_uint4(hw[0], hw[1], hw[2], hw[3]);
            dh[1] = make_uint4(hw[4], hw[5], hw[6], hw[7]);
            dl[0] = make_uint4(lw[0], lw[1], lw[2], lw[3]);
            dl[1] = make_uint4(lw[4], lw[5], lw[6], lw[7]);
        }
        // ---- B tile: copy pre-split W ----
        {
            const uint4* sh = (const uint4*)(g_Whi + (size_t)(k0 + bk) * H_ + n0 + bn);
            const uint4* slo= (const uint4*)(g_Wlo + (size_t)(k0 + bk) * H_ + n0 + bn);
            uint4* dh = (uint4*)(Bhi + bk * LDB + bn);
            uint4* dl = (uint4*)(Blo + bk * LDB + bn);
            dh[0] = sh[0]; dh[1] = sh[1];
            dl[0] = slo[0]; dl[1] = slo[1];
        }
        __syncthreads();

#pragma unroll
        for (int kt = 0; kt < 2; ++kt){
            const int ks = kt * 16;
            wmma::fragment<wmma::matrix_a, 16, 16, 16, __nv_bfloat16, wmma::row_major> fa_hi[2], fa_lo[2];
#pragma unroll
            for (int i = 0; i < 2; ++i){
                wmma::load_matrix_sync(fa_hi[i], Ahi + (wm*32 + i*16) * LDA + ks, LDA);
                wmma::load_matrix_sync(fa_lo[i], Alo + (wm*32 + i*16) * LDA + ks, LDA);
            }
            wmma::fragment<wmma::matrix_b, 16, 16, 16, __nv_bfloat16, wmma::row_major> fb_hi[4], fb_lo[4];
#pragma unroll
            for (int j = 0; j < 4; ++j){
                wmma::load_matrix_sync(fb_hi[j], Bhi + ks * LDB + wn*64 + j*16, LDB);
                wmma::load_matrix_sync(fb_lo[j], Blo + ks * LDB + wn*64 + j*16, LDB);
            }
#pragma unroll
            for (int i = 0; i < 2; ++i)
#pragma unroll
                for (int j = 0; j < 4; ++j){
                    wmma::mma_sync(acc[i][j], fa_hi[i], fb_hi[j], acc[i][j]);
                    wmma::mma_sync(acc[i][j], fa_hi[i], fb_lo[j], acc[i][j]);
                    wmma::mma_sync(acc[i][j], fa_lo[i], fb_hi[j], acc[i][j]);
                }
        }
        __syncthreads();
    }

    // ---- epilogue: plain store to feature buffer (bias added in gather) ----
#pragma unroll
    for (int i = 0; i < 2; ++i){
        const int row = m0 + wm * 32 + i * 16;
#pragma unroll
        for (int j = 0; j < 4; ++j){
            const int col = n0 + wn * 64 + j * 16;
            wmma::store_matrix_sync(
                g_feat + ((size_t)b * ND_ + row) * H_ + col,
                acc[i][j], H_, wmma::mem_row_major);
        }
    }
}

// ---------------- K6: gather-max (+bias) into output ----------------
__global__ void k_gather(float* __restrict__ out, const float* __restrict__ bias){
    const int wid = threadIdx.x >> 5, lane = threadIdx.x & 31;
    const int row = blockIdx.x * 8 + wid;
    float* op = out + (size_t)row * H_;
    const int c0 = lane * 4;
    const float4 z = make_float4(0.f, 0.f, 0.f, 0.f);
    const int deg = g_deg[row];
    if (!g_isup[row] || deg == 0){
        *(float4*)(op + c0) = z;
        *(float4*)(op + c0 + 128) = z;
        return;
    }
    const int off = g_off[row];
    const float NI = __int_as_float(0xff800000);
    float4 a = make_float4(NI, NI, NI, NI), bq = a;
    for (int e = 0; e < deg; ++e){
        const float* fp = g_feat + (size_t)g_src[off + e] * H_;
        float4 u = *(const float4*)(fp + c0);
        float4 v = *(const float4*)(fp + c0 + 128);
        a.x = fmaxf(a.x, u.x); a.y = fmaxf(a.y, u.y);
        a.z = fmaxf(a.z, u.z); a.w = fmaxf(a.w, u.w);
        bq.x = fmaxf(bq.x, v.x); bq.y = fmaxf(bq.y, v.y);
        bq.z = fmaxf(bq.z, v.z); bq.w = fmaxf(bq.w, v.w);
    }
    const float4 ba = *(const float4*)(bias + c0);
    const float4 bb = *(const float4*)(bias + c0 + 128);
    a.x += ba.x; a.y += ba.y; a.z += ba.z; a.w += ba.w;
    bq.x += bb.x; bq.y += bb.y; bq.z += bb.z; bq.w += bb.w;
    *(float4*)(op + c0) = a;
    *(float4*)(op + c0 + 128) = bq;
}

// ------------------------------- launch ------------------------------------
extern "C" void kernel_launch(void* const* d_in, const int* in_sizes, int n_in,
                              void* d_out, int out_size){
    const float* hh = (const float*)d_in[0];
    const float* sl = (const float*)d_in[1];
    const float* sc = (const float*)d_in[2];
    const float* W  = (const float*)d_in[3];
    const float* bb = (const float*)d_in[4];
    (void)in_sizes; (void)n_in;

    k_wsplit<<<(KP_*H_ + 255)/256, 256>>>(W);
    k_select<<<B_, 1024>>>(sc, (float*)d_out, (long long)out_size);
    dim3 gknn(ND_ / 256, B_);
    k_knn<<<gknn, 256>>>(sl);
    k_scan<<<1, 1024>>>();
    k_fill<<<(B_*ND_*M_ + 255)/256, 256>>>();
    dim3 gg(ND_ / BM_, H_ / BN_, B_);
    k_gemm_tc<<<gg, 256>>>(hh, sl, sc);
    k_gather<<<B_*N_/8, 256>>>((float*)d_out, bb);
}

// round 4
// speedup vs baseline: 1.7023x; 1.2465x over previous
#include <cuda_runtime.h>
#include <cuda_bf16.h>
#include <mma.h>
#include <cstdint>

using namespace nvcuda;

#define B_  8
#define N_  8192
#define H_  256
#define KD_ 260            // H + 4
#define KP_ 288            // K padded to 9*32
#define NU_ 2048
#define ND_ 6144
#define M_  5
#define EPG (ND_*M_)       // edges per graph = 30720
#define BM_ 128            // GEMM M tile
#define BN_ 128            // GEMM N tile
#define BK_ 32             // GEMM K tile
#define LDA 40             // smem A leading dim (pad)
#define LDB 136            // smem B leading dim (pad)

// ---------------- device scratch ----------------
__device__ int  g_up_idx[B_*NU_];
__device__ int  g_down_idx[B_*ND_];
__device__ int  g_dst[B_*ND_*M_];          // per edge: global up node id
__device__ unsigned char g_isup[B_*N_];
__device__ int  g_deg[B_*N_];
__device__ int  g_off[B_*N_];
__device__ int  g_cur[B_*N_];
__device__ int  g_src[B_*ND_*M_];          // CSR payload: down slot (b*ND+dl)
__device__ float g_feat[(size_t)B_*ND_*H_];           // 50 MB feature buffer
__device__ __nv_bfloat16 g_Whi[KP_*H_];
__device__ __nv_bfloat16 g_Wlo[KP_*H_];

__device__ __forceinline__ unsigned enc_f(float f){
    unsigned u = __float_as_uint(f);
    return (u & 0x80000000u) ? ~u : (u | 0x80000000u);
}

__device__ __forceinline__ int block_scan_excl(int val, int* s_part, int tid){
    s_part[tid] = val;
    __syncthreads();
    for (int off = 1; off < 1024; off <<= 1){
        int v = (tid >= off) ? s_part[tid - off] : 0;
        __syncthreads();
        s_part[tid] += v;
        __syncthreads();
    }
    return s_part[tid] - val;
}

// ---------------- K0: W split into hi/lo bf16 (row-major, K padded) --------
__global__ void k_wsplit(const float* __restrict__ W){
    const int idx = blockIdx.x * 256 + threadIdx.x;   // KP_*H_ = 73728
    if (idx >= KP_ * H_) return;
    const int k = idx / H_, n = idx % H_;
    const float w = (k < KD_) ? W[k * H_ + n] : 0.0f;
    const __nv_bfloat16 hi = __float2bfloat16(w);
    const __nv_bfloat16 lo = __float2bfloat16(w - __bfloat162float(hi));
    g_Whi[idx] = hi;
    g_Wlo[idx] = lo;
}

// ---------------- K1: top-25% selection + compaction ----------------
__global__ void k_select(const float* __restrict__ scores,
                         float* __restrict__ d_out, long long out_size){
    __shared__ unsigned s_enc[N_];
    __shared__ int s_part[1024];
    __shared__ int s_hist[16];
    __shared__ int s_bcast[2];
    const int b = blockIdx.x, tid = threadIdx.x;

    for (int i = tid; i < N_; i += 1024) g_deg[b * N_ + i] = 0;

    const float* sc = scores + (long long)b * N_;
    for (int i = tid; i < N_; i += 1024) s_enc[i] = enc_f(sc[i]);
    __syncthreads();

    unsigned prefix = 0, known = 0;
    int k = NU_;
    for (int lvl = 7; lvl >= 0; --lvl){
        if (tid < 16) s_hist[tid] = 0;
        __syncthreads();
        const int sh = lvl * 4;
        for (int i = tid; i < N_; i += 1024){
            unsigned e = s_enc[i];
            if ((e & known) == prefix) atomicAdd(&s_hist[(e >> sh) & 15], 1);
        }
        __syncthreads();
        if (tid == 0){
            int kk = k, bin = 15;
            while (bin > 0 && kk > s_hist[bin]) { kk -= s_hist[bin]; --bin; }
            s_bcast[0] = bin; s_bcast[1] = kk;
        }
        __syncthreads();
        prefix |= ((unsigned)s_bcast[0]) << sh;
        known  |= 0xFu << sh;
        k = s_bcast[1];
        __syncthreads();
    }
    const unsigned T = prefix;

    if (tid == 0) s_bcast[0] = 0;
    __syncthreads();
    {
        int loc = 0;
        for (int i = tid; i < N_; i += 1024) if (s_enc[i] > T) loc++;
        atomicAdd(&s_bcast[0], loc);
    }
    __syncthreads();
    const int need_eq = NU_ - s_bcast[0];
    __syncthreads();

    const int base = tid * 8;
    int eqc = 0;
#pragma unroll
    for (int e = 0; e < 8; ++e) eqc += (s_enc[base + e] == T);
    int eqbase = block_scan_excl(eqc, s_part, tid);

    unsigned mbits = 0; int upc = 0;
    {
        int ec = eqbase;
#pragma unroll
        for (int e = 0; e < 8; ++e){
            unsigned v = s_enc[base + e];
            bool msk;
            if (v > T) msk = true;
            else if (v == T) { msk = (ec < need_eq); ec++; }
            else msk = false;
            if (msk) { mbits |= (1u << e); upc++; }
        }
    }
    __syncthreads();
    int upbase = block_scan_excl(upc, s_part, tid);

    const long long BNH = (long long)B_ * N_ * H_;
    const bool wf = (out_size == BNH + (long long)B_ * N_);
    const bool wb = (out_size == BNH + ((long long)B_ * N_) / 4);
    int up = upbase;
#pragma unroll
    for (int e = 0; e < 8; ++e){
        const int i = base + e;
        const bool msk = (mbits >> e) & 1;
        if (msk) { g_up_idx[b * NU_ + up] = i; up++; }
        else       g_down_idx[b * ND_ + (i - up)] = i;
        g_isup[b * N_ + i] = msk ? 1 : 0;
        if (wf)      d_out[BNH + (long long)b * N_ + i] = msk ? 1.0f : 0.0f;
        else if (wb) ((unsigned char*)d_out)[BNH * 4 + (long long)b * N_ + i] = msk ? 1 : 0;
    }
}

// -------- K2: directional 5-NN + degree count (float4, 2 pts/thread) --------
struct Top5 { float d0,d1,d2,d3,d4; int i0,i1,i2,i3,i4; };
__device__ __forceinline__ void top5_init(Top5& t){
    const float INF = __int_as_float(0x7f800000);
    t.d0=t.d1=t.d2=t.d3=t.d4=INF; t.i0=t.i1=t.i2=t.i3=t.i4=0;
}
__device__ __forceinline__ void top5_ins(Top5& t, float d, int j){
    if (d < t.d4){
        if (d < t.d3){ t.d4=t.d3; t.i4=t.i3;
            if (d < t.d2){ t.d3=t.d2; t.i3=t.i2;
                if (d < t.d1){ t.d2=t.d1; t.i2=t.i1;
                    if (d < t.d0){ t.d1=t.d0; t.i1=t.i0; t.d0=d; t.i0=j; }
                    else        { t.d1=d;  t.i1=j; }
                } else { t.d2=d; t.i2=j; }
            } else { t.d3=d; t.i3=j; }
        } else { t.d4=d; t.i4=j; }
    }
}

__global__ void k_knn(const float* __restrict__ s_l){
    __shared__ float4 su[NU_];   // xyz + global idx in .w bits
    const int b = blockIdx.y;
    const int tid = threadIdx.x;
    for (int j = tid; j < NU_; j += 256){
        int u = g_up_idx[b * NU_ + j];
        long long p = ((long long)b * N_ + u) * 3;
        su[j] = make_float4(s_l[p], s_l[p+1], s_l[p+2], __int_as_float(b * N_ + u));
    }
    __syncthreads();

    const int dlA = blockIdx.x * 512 + tid;
    const int dlB = dlA + 256;
    const int dnA = g_down_idx[b * ND_ + dlA];
    const int dnB = g_down_idx[b * ND_ + dlB];
    long long pA = ((long long)b * N_ + dnA) * 3;
    long long pB = ((long long)b * N_ + dnB) * 3;
    const float xA = s_l[pA], yA = s_l[pA+1], zA = s_l[pA+2];
    const float xB = s_l[pB], yB = s_l[pB+1], zB = s_l[pB+2];

    Top5 tA, tB; top5_init(tA); top5_init(tB);
    for (int j = 0; j < NU_; ++j){
        const float4 u = su[j];
        float dxA = xA-u.x, dyA = yA-u.y, dzA = zA-u.z;
        float dxB = xB-u.x, dyB = yB-u.y, dzB = zB-u.z;
        float dA = dxA*dxA + dyA*dyA + dzA*dzA;
        float dB = dxB*dxB + dyB*dyB + dzB*dzB;
        top5_ins(tA, dA, j);
        top5_ins(tB, dB, j);
    }

    {
        int* dst = g_dst + ((long long)b * ND_ + dlA) * M_;
        int e0=__float_as_int(su[tA.i0].w), e1=__float_as_int(su[tA.i1].w),
            e2=__float_as_int(su[tA.i2].w), e3=__float_as_int(su[tA.i3].w),
            e4=__float_as_int(su[tA.i4].w);
        dst[0]=e0; dst[1]=e1; dst[2]=e2; dst[3]=e3; dst[4]=e4;
        atomicAdd(&g_deg[e0],1); atomicAdd(&g_deg[e1],1); atomicAdd(&g_deg[e2],1);
        atomicAdd(&g_deg[e3],1); atomicAdd(&g_deg[e4],1);
    }
    {
        int* dst = g_dst + ((long long)b * ND_ + dlB) * M_;
        int e0=__float_as_int(su[tB.i0].w), e1=__float_as_int(su[tB.i1].w),
            e2=__float_as_int(su[tB.i2].w), e3=__float_as_int(su[tB.i3].w),
            e4=__float_as_int(su[tB.i4].w);
        dst[0]=e0; dst[1]=e1; dst[2]=e2; dst[3]=e3; dst[4]=e4;
        atomicAdd(&g_deg[e0],1); atomicAdd(&g_deg[e1],1); atomicAdd(&g_deg[e2],1);
        atomicAdd(&g_deg[e3],1); atomicAdd(&g_deg[e4],1);
    }
}

// -------- K3: per-graph exclusive scan (graph b owns edges [b*EPG, ...)) ----
__global__ void k_scan(){
    __shared__ int sp[1024];
    const int b = blockIdx.x, tid = threadIdx.x;
    const int base = b * N_ + tid * 8;
    int d[8]; int s = 0;
#pragma unroll
    for (int i = 0; i < 8; ++i){ d[i] = g_deg[base + i]; s += d[i]; }
    int run = block_scan_excl(s, sp, tid) + b * EPG;
#pragma unroll
    for (int i = 0; i < 8; ++i){
        g_off[base + i] = run;
        g_cur[base + i] = run;
        run += d[i];
    }
}

// ---------------- K4: CSR fill ----------------
__global__ void k_fill(){
    const int e = blockIdx.x * 256 + threadIdx.x;
    if (e >= B_ * ND_ * M_) return;
    const int dst = g_dst[e];
    const int pos = atomicAdd(&g_cur[dst], 1);
    g_src[pos] = e / M_;
}

// -------- K5: WMMA bf16 hi/lo GEMM: g_feat[down rows] = X @ W (no bias) ----
__global__ void __launch_bounds__(256)
k_gemm_tc(const float* __restrict__ hh, const float* __restrict__ sl,
          const float* __restrict__ sc){
    __shared__ __nv_bfloat16 Ahi[BM_ * LDA];
    __shared__ __nv_bfloat16 Alo[BM_ * LDA];
    __shared__ __nv_bfloat16 Bhi[BK_ * LDB];
    __shared__ __nv_bfloat16 Blo[BK_ * LDB];
    __shared__ int s_g[BM_];

    const int b   = blockIdx.z;
    const int m0  = blockIdx.x * BM_;
    const int n0  = blockIdx.y * BN_;
    const int tid = threadIdx.x;
    const int w   = tid >> 5;
    const int wm  = w >> 1;
    const int wn  = w & 1;

    if (tid < BM_) s_g[tid] = b * N_ + g_down_idx[b * ND_ + m0 + tid];
    __syncthreads();

    wmma::fragment<wmma::accumulator, 16, 16, 16, float> acc[2][4];
#pragma unroll
    for (int i = 0; i < 2; ++i)
#pragma unroll
        for (int j = 0; j < 4; ++j) wmma::fill_fragment(acc[i][j], 0.0f);

    const int ar  = tid >> 1;
    const int ah  = (tid & 1) * 16;
    const int g   = s_g[ar];
    const int bk  = tid >> 3;
    const int bn  = (tid & 7) * 16;

    for (int c = 0; c < KP_ / BK_; ++c){
        const int k0 = c * BK_;
        float xs[16];
        if (c < 8){
            const float4* hp = (const float4*)(hh + (size_t)g * H_ + k0 + ah);
#pragma unroll
            for (int q = 0; q < 4; ++q){
                float4 f = hp[q];
                xs[4*q] = f.x; xs[4*q+1] = f.y; xs[4*q+2] = f.z; xs[4*q+3] = f.w;
            }
        } else {
#pragma unroll
            for (int q = 0; q < 16; ++q) xs[q] = 0.0f;
            if (ah == 0){
                xs[0] = sl[(size_t)g * 3];
                xs[1] = sl[(size_t)g * 3 + 1];
                xs[2] = sl[(size_t)g * 3 + 2];
                xs[3] = sc[g];
            }
        }
        unsigned hw[8], lw[8];
#pragma unroll
        for (int q = 0; q < 8; ++q){
            __nv_bfloat16 h0 = __float2bfloat16(xs[2*q]);
            __nv_bfloat16 h1 = __float2bfloat16(xs[2*q+1]);
            __nv_bfloat16 l0 = __float2bfloat16(xs[2*q]   - __bfloat162float(h0));
            __nv_bfloat16 l1 = __float2bfloat16(xs[2*q+1] - __bfloat162float(h1));
            __nv_bfloat162 hp2 = __nv_bfloat162(h0, h1);
            __nv_bfloat162 lp2 = __nv_bfloat162(l0, l1);
            hw[q] = *(unsigned*)&hp2;
            lw[q] = *(unsigned*)&lp2;
        }
        {
            uint4* dh = (uint4*)(Ahi + ar * LDA + ah);
            uint4* dl = (uint4*)(Alo + ar * LDA + ah);
            dh[0] = make_uint4(hw[0], hw[1], hw[2], hw[3]);
            dh[1] = make_uint4(hw[4], hw[5], hw[6], hw[7]);
            dl[0] = make_uint4(lw[0], lw[1], lw[2], lw[3]);
            dl[1] = make_uint4(lw[4], lw[5], lw[6], lw[7]);
        }
        {
            const uint4* sh = (const uint4*)(g_Whi + (size_t)(k0 + bk) * H_ + n0 + bn);
            const uint4* slo= (const uint4*)(g_Wlo + (size_t)(k0 + bk) * H_ + n0 + bn);
            uint4* dh = (uint4*)(Bhi + bk * LDB + bn);
            uint4* dl = (uint4*)(Blo + bk * LDB + bn);
            dh[0] = sh[0]; dh[1] = sh[1];
            dl[0] = slo[0]; dl[1] = slo[1];
        }
        __syncthreads();

#pragma unroll
        for (int kt = 0; kt < 2; ++kt){
            const int ks = kt * 16;
            wmma::fragment<wmma::matrix_a, 16, 16, 16, __nv_bfloat16, wmma::row_major> fa_hi[2], fa_lo[2];
#pragma unroll
            for (int i = 0; i < 2; ++i){
                wmma::load_matrix_sync(fa_hi[i], Ahi + (wm*32 + i*16) * LDA + ks, LDA);
                wmma::load_matrix_sync(fa_lo[i], Alo + (wm*32 + i*16) * LDA + ks, LDA);
            }
            wmma::fragment<wmma::matrix_b, 16, 16, 16, __nv_bfloat16, wmma::row_major> fb_hi[4], fb_lo[4];
#pragma unroll
            for (int j = 0; j < 4; ++j){
                wmma::load_matrix_sync(fb_hi[j], Bhi + ks * LDB + wn*64 + j*16, LDB);
                wmma::load_matrix_sync(fb_lo[j], Blo + ks * LDB + wn*64 + j*16, LDB);
            }
#pragma unroll
            for (int i = 0; i < 2; ++i)
#pragma unroll
                for (int j = 0; j < 4; ++j){
                    wmma::mma_sync(acc[i][j], fa_hi[i], fb_hi[j], acc[i][j]);
                    wmma::mma_sync(acc[i][j], fa_hi[i], fb_lo[j], acc[i][j]);
                    wmma::mma_sync(acc[i][j], fa_lo[i], fb_hi[j], acc[i][j]);
                }
        }
        __syncthreads();
    }

#pragma unroll
    for (int i = 0; i < 2; ++i){
        const int row = m0 + wm * 32 + i * 16;
#pragma unroll
        for (int j = 0; j < 4; ++j){
            const int col = n0 + wn * 64 + j * 16;
            wmma::store_matrix_sync(
                g_feat + ((size_t)b * ND_ + row) * H_ + col,
                acc[i][j], H_, wmma::mem_row_major);
        }
    }
}

// ---------------- K6: gather-max (+bias) into output ----------------
__global__ void k_gather(float* __restrict__ out, const float* __restrict__ bias){
    const int wid = threadIdx.x >> 5, lane = threadIdx.x & 31;
    const int row = blockIdx.x * 8 + wid;
    float* op = out + (size_t)row * H_;
    const int c0 = lane * 4;
    const float4 z = make_float4(0.f, 0.f, 0.f, 0.f);
    const int deg = g_deg[row];
    if (!g_isup[row] || deg == 0){
        *(float4*)(op + c0) = z;
        *(float4*)(op + c0 + 128) = z;
        return;
    }
    const int off = g_off[row];
    const float NI = __int_as_float(0xff800000);
    float4 a = make_float4(NI, NI, NI, NI), bq = a;
    for (int e = 0; e < deg; ++e){
        const float* fp = g_feat + (size_t)g_src[off + e] * H_;
        float4 u = *(const float4*)(fp + c0);
        float4 v = *(const float4*)(fp + c0 + 128);
        a.x = fmaxf(a.x, u.x); a.y = fmaxf(a.y, u.y);
        a.z = fmaxf(a.z, u.z); a.w = fmaxf(a.w, u.w);
        bq.x = fmaxf(bq.x, v.x); bq.y = fmaxf(bq.y, v.y);
        bq.z = fmaxf(bq.z, v.z); bq.w = fmaxf(bq.w, v.w);
    }
    const float4 ba = *(const float4*)(bias + c0);
    const float4 bb = *(const float4*)(bias + c0 + 128);
    a.x += ba.x; a.y += ba.y; a.z += ba.z; a.w += ba.w;
    bq.x += bb.x; bq.y += bb.y; bq.z += bb.z; bq.w += bb.w;
    *(float4*)(op + c0) = a;
    *(float4*)(op + c0 + 128) = bq;
}

// ------------------------------- launch ------------------------------------
extern "C" void kernel_launch(void* const* d_in, const int* in_sizes, int n_in,
                              void* d_out, int out_size){
    const float* hh = (const float*)d_in[0];
    const float* sl = (const float*)d_in[1];
    const float* sc = (const float*)d_in[2];
    const float* W  = (const float*)d_in[3];
    const float* bb = (const float*)d_in[4];
    (void)in_sizes; (void)n_in;

    k_wsplit<<<(KP_*H_ + 255)/256, 256>>>(W);
    k_select<<<B_, 1024>>>(sc, (float*)d_out, (long long)out_size);
    dim3 gknn(ND_ / 512, B_);
    k_knn<<<gknn, 256>>>(sl);
    k_scan<<<B_, 1024>>>();
    k_fill<<<(B_*ND_*M_ + 255)/256, 256>>>();
    dim3 gg(ND_ / BM_, H_ / BN_, B_);
    k_gemm_tc<<<gg, 256>>>(hh, sl, sc);
    k_gather<<<B_*N_/8, 256>>>((float*)d_out, bb);
}

// round 5
// speedup vs baseline: 1.7113x; 1.0053x over previous
#include <cuda_runtime.h>
#include <cuda_bf16.h>
#include <mma.h>
#include <cstdint>

using namespace nvcuda;

#define B_  8
#define N_  8192
#define H_  256
#define KD_ 260            // H + 4
#define KP_ 288            // K padded to 9*32
#define NU_ 2048
#define ND_ 6144
#define M_  5
#define EPG (ND_*M_)       // edges per graph = 30720
#define BM2 64             // GEMM M tile
#define BN2 256            // GEMM N tile (= H, one tile)
#define LDA2 40
#define LDB2 264
// dynamic smem byte offsets (2-stage pipeline)
#define OFF_AHI(s) ((s)*5120)
#define OFF_ALO(s) (10240 + (s)*5120)
#define OFF_BHI(s) (20480 + (s)*16896)
#define OFF_BLO(s) (54272 + (s)*16896)
#define SMEM_G 88064

// ---------------- device scratch ----------------
__device__ int  g_up_idx[B_*NU_];
__device__ int  g_down_idx[B_*ND_];
__device__ int  g_dst[B_*ND_*M_];
__device__ unsigned char g_isup[B_*N_];
__device__ int  g_deg[B_*N_];
__device__ int  g_off[B_*N_];
__device__ int  g_cur[B_*N_];
__device__ int  g_src[B_*ND_*M_];
__device__ float g_feat[(size_t)B_*ND_*H_];
__device__ __nv_bfloat16 g_Whi[KP_*H_];
__device__ __nv_bfloat16 g_Wlo[KP_*H_];

__device__ __forceinline__ unsigned enc_f(float f){
    unsigned u = __float_as_uint(f);
    return (u & 0x80000000u) ? ~u : (u | 0x80000000u);
}
__device__ __forceinline__ void cpa16(void* dst, const void* src){
    unsigned d = (unsigned)__cvta_generic_to_shared(dst);
    asm volatile("cp.async.cg.shared.global [%0], [%1], 16;" :: "r"(d), "l"(src));
}
__device__ __forceinline__ int block_scan_excl(int val, int* s_part, int tid){
    s_part[tid] = val;
    __syncthreads();
    for (int off = 1; off < 1024; off <<= 1){
        int v = (tid >= off) ? s_part[tid - off] : 0;
        __syncthreads();
        s_part[tid] += v;
        __syncthreads();
    }
    return s_part[tid] - val;
}

// ---------------- K0: W split into hi/lo bf16 ----------------
__global__ void k_wsplit(const float* __restrict__ W){
    const int idx = blockIdx.x * 256 + threadIdx.x;
    if (idx >= KP_ * H_) return;
    const int k = idx / H_, n = idx % H_;
    const float w = (k < KD_) ? W[k * H_ + n] : 0.0f;
    const __nv_bfloat16 hi = __float2bfloat16(w);
    const __nv_bfloat16 lo = __float2bfloat16(w - __bfloat162float(hi));
    g_Whi[idx] = hi;
    g_Wlo[idx] = lo;
}

// ---------------- K1: top-25% selection (8-bit radix, 256 bins) ------------
__global__ void k_select(const float* __restrict__ scores,
                         float* __restrict__ d_out, long long out_size){
    __shared__ unsigned s_enc[N_];
    __shared__ int s_part[1024];
    __shared__ int s_hist[256];
    __shared__ int s_bcast[2];
    const int b = blockIdx.x, tid = threadIdx.x;

    for (int i = tid; i < N_; i += 1024) g_deg[b * N_ + i] = 0;

    const float* sc = scores + (long long)b * N_;
    for (int i = tid; i < N_; i += 1024) s_enc[i] = enc_f(sc[i]);
    __syncthreads();

    unsigned prefix = 0, known = 0;
    int k = NU_;
    for (int lvl = 3; lvl >= 0; --lvl){
        if (tid < 256) s_hist[tid] = 0;
        __syncthreads();
        const int sh = lvl * 8;
        for (int i = tid; i < N_; i += 1024){
            unsigned e = s_enc[i];
            if ((e & known) == prefix) atomicAdd(&s_hist[(e >> sh) & 255], 1);
        }
        __syncthreads();
        if (tid == 0){
            int kk = k, bin = 255;
            while (bin > 0 && kk > s_hist[bin]) { kk -= s_hist[bin]; --bin; }
            s_bcast[0] = bin; s_bcast[1] = kk;
        }
        __syncthreads();
        prefix |= ((unsigned)s_bcast[0]) << sh;
        known  |= 0xFFu << sh;
        k = s_bcast[1];
        __syncthreads();
    }
    const unsigned T = prefix;

    if (tid == 0) s_bcast[0] = 0;
    __syncthreads();
    {
        int loc = 0;
        for (int i = tid; i < N_; i += 1024) if (s_enc[i] > T) loc++;
        atomicAdd(&s_bcast[0], loc);
    }
    __syncthreads();
    const int need_eq = NU_ - s_bcast[0];
    __syncthreads();

    const int base = tid * 8;
    int eqc = 0;
#pragma unroll
    for (int e = 0; e < 8; ++e) eqc += (s_enc[base + e] == T);
    int eqbase = block_scan_excl(eqc, s_part, tid);

    unsigned mbits = 0; int upc = 0;
    {
        int ec = eqbase;
#pragma unroll
        for (int e = 0; e < 8; ++e){
            unsigned v = s_enc[base + e];
            bool msk;
            if (v > T) msk = true;
            else if (v == T) { msk = (ec < need_eq); ec++; }
            else msk = false;
            if (msk) { mbits |= (1u << e); upc++; }
        }
    }
    __syncthreads();
    int upbase = block_scan_excl(upc, s_part, tid);

    const long long BNH = (long long)B_ * N_ * H_;
    const bool wf = (out_size == BNH + (long long)B_ * N_);
    const bool wb = (out_size == BNH + ((long long)B_ * N_) / 4);
    int up = upbase;
#pragma unroll
    for (int e = 0; e < 8; ++e){
        const int i = base + e;
        const bool msk = (mbits >> e) & 1;
        if (msk) { g_up_idx[b * NU_ + up] = i; up++; }
        else       g_down_idx[b * ND_ + (i - up)] = i;
        g_isup[b * N_ + i] = msk ? 1 : 0;
        if (wf)      d_out[BNH + (long long)b * N_ + i] = msk ? 1.0f : 0.0f;
        else if (wb) ((unsigned char*)d_out)[BNH * 4 + (long long)b * N_ + i] = msk ? 1 : 0;
    }
}

// -------- K2: directional 5-NN + degree count --------
struct Top5 { float d0,d1,d2,d3,d4; int i0,i1,i2,i3,i4; };
__device__ __forceinline__ void top5_init(Top5& t){
    const float INF = __int_as_float(0x7f800000);
    t.d0=t.d1=t.d2=t.d3=t.d4=INF; t.i0=t.i1=t.i2=t.i3=t.i4=0;
}
__device__ __forceinline__ void top5_ins(Top5& t, float d, int j){
    if (d < t.d4){
        if (d < t.d3){ t.d4=t.d3; t.i4=t.i3;
            if (d < t.d2){ t.d3=t.d2; t.i3=t.i2;
                if (d < t.d1){ t.d2=t.d1; t.i2=t.i1;
                    if (d < t.d0){ t.d1=t.d0; t.i1=t.i0; t.d0=d; t.i0=j; }
                    else        { t.d1=d;  t.i1=j; }
                } else { t.d2=d; t.i2=j; }
            } else { t.d3=d; t.i3=j; }
        } else { t.d4=d; t.i4=j; }
    }
}

__global__ void k_knn(const float* __restrict__ s_l){
    __shared__ float4 su[NU_];
    const int b = blockIdx.y;
    const int tid = threadIdx.x;
    for (int j = tid; j < NU_; j += 256){
        int u = g_up_idx[b * NU_ + j];
        long long p = ((long long)b * N_ + u) * 3;
        su[j] = make_float4(s_l[p], s_l[p+1], s_l[p+2], __int_as_float(b * N_ + u));
    }
    __syncthreads();

    const int dlA = blockIdx.x * 512 + tid;
    const int dlB = dlA + 256;
    const int dnA = g_down_idx[b * ND_ + dlA];
    const int dnB = g_down_idx[b * ND_ + dlB];
    long long pA = ((long long)b * N_ + dnA) * 3;
    long long pB = ((long long)b * N_ + dnB) * 3;
    const float xA = s_l[pA], yA = s_l[pA+1], zA = s_l[pA+2];
    const float xB = s_l[pB], yB = s_l[pB+1], zB = s_l[pB+2];

    Top5 tA, tB; top5_init(tA); top5_init(tB);
    for (int j = 0; j < NU_; ++j){
        const float4 u = su[j];
        float dxA = xA-u.x, dyA = yA-u.y, dzA = zA-u.z;
        float dxB = xB-u.x, dyB = yB-u.y, dzB = zB-u.z;
        float dA = dxA*dxA + dyA*dyA + dzA*dzA;
        float dB = dxB*dxB + dyB*dyB + dzB*dzB;
        top5_ins(tA, dA, j);
        top5_ins(tB, dB, j);
    }
    {
        int* dst = g_dst + ((long long)b * ND_ + dlA) * M_;
        int e0=__float_as_int(su[tA.i0].w), e1=__float_as_int(su[tA.i1].w),
            e2=__float_as_int(su[tA.i2].w), e3=__float_as_int(su[tA.i3].w),
            e4=__float_as_int(su[tA.i4].w);
        dst[0]=e0; dst[1]=e1; dst[2]=e2; dst[3]=e3; dst[4]=e4;
        atomicAdd(&g_deg[e0],1); atomicAdd(&g_deg[e1],1); atomicAdd(&g_deg[e2],1);
        atomicAdd(&g_deg[e3],1); atomicAdd(&g_deg[e4],1);
    }
    {
        int* dst = g_dst + ((long long)b * ND_ + dlB) * M_;
        int e0=__float_as_int(su[tB.i0].w), e1=__float_as_int(su[tB.i1].w),
            e2=__float_as_int(su[tB.i2].w), e3=__float_as_int(su[tB.i3].w),
            e4=__float_as_int(su[tB.i4].w);
        dst[0]=e0; dst[1]=e1; dst[2]=e2; dst[3]=e3; dst[4]=e4;
        atomicAdd(&g_deg[e0],1); atomicAdd(&g_deg[e1],1); atomicAdd(&g_deg[e2],1);
        atomicAdd(&g_deg[e3],1); atomicAdd(&g_deg[e4],1);
    }
}

// -------- K3: per-graph exclusive scan --------
__global__ void k_scan(){
    __shared__ int sp[1024];
    const int b = blockIdx.x, tid = threadIdx.x;
    const int base = b * N_ + tid * 8;
    int d[8]; int s = 0;
#pragma unroll
    for (int i = 0; i < 8; ++i){ d[i] = g_deg[base + i]; s += d[i]; }
    int run = block_scan_excl(s, sp, tid) + b * EPG;
#pragma unroll
    for (int i = 0; i < 8; ++i){
        g_off[base + i] = run;
        g_cur[base + i] = run;
        run += d[i];
    }
}

// ---------------- K4: CSR fill ----------------
__global__ void k_fill(){
    const int e = blockIdx.x * 256 + threadIdx.x;
    if (e >= B_ * ND_ * M_) return;
    const int dst = g_dst[e];
    const int pos = atomicAdd(&g_cur[dst], 1);
    g_src[pos] = e / M_;
}

// -------- K5: pipelined WMMA bf16 hi/lo GEMM, BM=64 x BN=256 --------
__device__ __forceinline__ void loadA_regs(float* xs, const float* __restrict__ hh,
                                           const float* __restrict__ sl,
                                           const float* __restrict__ sc,
                                           int g, int c, int ah){
    if (c < 8){
        const float4* hp = (const float4*)(hh + (size_t)g * H_ + c * 32 + ah);
        float4 f0 = hp[0], f1 = hp[1];
        xs[0]=f0.x; xs[1]=f0.y; xs[2]=f0.z; xs[3]=f0.w;
        xs[4]=f1.x; xs[5]=f1.y; xs[6]=f1.z; xs[7]=f1.w;
    } else {
#pragma unroll
        for (int q = 0; q < 8; ++q) xs[q] = 0.0f;
        if (ah == 0){
            xs[0] = sl[(size_t)g * 3];
            xs[1] = sl[(size_t)g * 3 + 1];
            xs[2] = sl[(size_t)g * 3 + 2];
            xs[3] = sc[g];
        }
    }
}

__global__ void __launch_bounds__(256)
k_gemm_tc(const float* __restrict__ hh, const float* __restrict__ sl,
          const float* __restrict__ sc){
    extern __shared__ char sm[];
    __shared__ int s_g[BM2];

    const int b   = blockIdx.y;
    const int m0  = blockIdx.x * BM2;
    const int tid = threadIdx.x;
    const int w   = tid >> 5;
    const int wm  = w >> 2;          // 0..1 -> rows wm*32
    const int wn  = w & 3;           // 0..3 -> cols wn*64

    if (tid < BM2) s_g[tid] = b * N_ + g_down_idx[b * ND_ + m0 + tid];
    __syncthreads();

    const int ar = tid >> 2;         // 0..63
    const int ah = (tid & 3) * 8;    // 0,8,16,24
    const int g  = s_g[ar];

    wmma::fragment<wmma::accumulator, 16, 16, 16, float> acc[2][4];
#pragma unroll
    for (int i = 0; i < 2; ++i)
#pragma unroll
        for (int j = 0; j < 4; ++j) wmma::fill_fragment(acc[i][j], 0.0f);

    // B copy mapping: 1024 16B-chunks per matrix, 4 per thread
    auto copyB = [&](int c, int s){
        const int k0 = c * 32;
        __nv_bfloat16* Bh = (__nv_bfloat16*)(sm + OFF_BHI(s));
        __nv_bfloat16* Bl = (__nv_bfloat16*)(sm + OFF_BLO(s));
#pragma unroll
        for (int q = 0; q < 4; ++q){
            const int i = tid + q * 256;
            const int row = i >> 5;
            const int col = (i & 31) * 8;
            cpa16(Bh + row * LDB2 + col, g_Whi + (size_t)(k0 + row) * H_ + col);
            cpa16(Bl + row * LDB2 + col, g_Wlo + (size_t)(k0 + row) * H_ + col);
        }
        asm volatile("cp.async.commit_group;");
    };
    auto storeA = [&](const float* xs, int s){
        unsigned hw[4], lw[4];
#pragma unroll
        for (int q = 0; q < 4; ++q){
            __nv_bfloat16 h0 = __float2bfloat16(xs[2*q]);
            __nv_bfloat16 h1 = __float2bfloat16(xs[2*q+1]);
            __nv_bfloat16 l0 = __float2bfloat16(xs[2*q]   - __bfloat162float(h0));
            __nv_bfloat16 l1 = __float2bfloat16(xs[2*q+1] - __bfloat162float(h1));
            __nv_bfloat162 hp2 = __nv_bfloat162(h0, h1);
            __nv_bfloat162 lp2 = __nv_bfloat162(l0, l1);
            hw[q] = *(unsigned*)&hp2;
            lw[q] = *(unsigned*)&lp2;
        }
        *(uint4*)((__nv_bfloat16*)(sm + OFF_AHI(s)) + ar * LDA2 + ah) =
            make_uint4(hw[0], hw[1], hw[2], hw[3]);
        *(uint4*)((__nv_bfloat16*)(sm + OFF_ALO(s)) + ar * LDA2 + ah) =
            make_uint4(lw[0], lw[1], lw[2], lw[3]);
    };

    float xs[8], xs2[8];
    loadA_regs(xs, hh, sl, sc, g, 0, ah);
    copyB(0, 0);

    for (int c = 0; c < 9; ++c){
        const int s = c & 1;
        if (c < 8){
            loadA_regs(xs2, hh, sl, sc, g, c + 1, ah);
            copyB(c + 1, s ^ 1);
        }
        storeA(xs, s);
        if (c < 8) asm volatile("cp.async.wait_group 1;");
        else       asm volatile("cp.async.wait_group 0;");
        __syncthreads();

        const __nv_bfloat16* Ah = (const __nv_bfloat16*)(sm + OFF_AHI(s));
        const __nv_bfloat16* Al = (const __nv_bfloat16*)(sm + OFF_ALO(s));
        const __nv_bfloat16* Bh = (const __nv_bfloat16*)(sm + OFF_BHI(s));
        const __nv_bfloat16* Bl = (const __nv_bfloat16*)(sm + OFF_BLO(s));
#pragma unroll
        for (int kt = 0; kt < 2; ++kt){
            const int ks = kt * 16;
            wmma::fragment<wmma::matrix_a, 16, 16, 16, __nv_bfloat16, wmma::row_major> fa_hi[2], fa_lo[2];
#pragma unroll
            for (int i = 0; i < 2; ++i){
                wmma::load_matrix_sync(fa_hi[i], Ah + (wm*32 + i*16) * LDA2 + ks, LDA2);
                wmma::load_matrix_sync(fa_lo[i], Al + (wm*32 + i*16) * LDA2 + ks, LDA2);
            }
#pragma unroll
            for (int j = 0; j < 4; ++j){
                wmma::fragment<wmma::matrix_b, 16, 16, 16, __nv_bfloat16, wmma::row_major> fb_hi, fb_lo;
                wmma::load_matrix_sync(fb_hi, Bh + ks * LDB2 + wn*64 + j*16, LDB2);
                wmma::load_matrix_sync(fb_lo, Bl + ks * LDB2 + wn*64 + j*16, LDB2);
#pragma unroll
                for (int i = 0; i < 2; ++i){
                    wmma::mma_sync(acc[i][j], fa_hi[i], fb_hi, acc[i][j]);
                    wmma::mma_sync(acc[i][j], fa_hi[i], fb_lo, acc[i][j]);
                    wmma::mma_sync(acc[i][j], fa_lo[i], fb_hi, acc[i][j]);
                }
            }
        }
        __syncthreads();
#pragma unroll
        for (int q = 0; q < 8; ++q) xs[q] = xs2[q];
    }

#pragma unroll
    for (int i = 0; i < 2; ++i){
        const int row = m0 + wm * 32 + i * 16;
#pragma unroll
        for (int j = 0; j < 4; ++j){
            const int col = wn * 64 + j * 16;
            wmma::store_matrix_sync(
                g_feat + ((size_t)b * ND_ + row) * H_ + col,
                acc[i][j], H_, wmma::mem_row_major);
        }
    }
}

// ---------------- K6: gather-max (+bias) into output ----------------
__global__ void k_gather(float* __restrict__ out, const float* __restrict__ bias){
    const int wid = threadIdx.x >> 5, lane = threadIdx.x & 31;
    const int row = blockIdx.x * 8 + wid;
    float* op = out + (size_t)row * H_;
    const int c0 = lane * 4;
    const float4 z = make_float4(0.f, 0.f, 0.f, 0.f);
    const int deg = g_deg[row];
    if (!g_isup[row] || deg == 0){
        *(float4*)(op + c0) = z;
        *(float4*)(op + c0 + 128) = z;
        return;
    }
    const int off = g_off[row];
    const float NI = __int_as_float(0xff800000);
    float4 a = make_float4(NI, NI, NI, NI), bq = a;
    for (int e = 0; e < deg; ++e){
        const float* fp = g_feat + (size_t)g_src[off + e] * H_;
        float4 u = *(const float4*)(fp + c0);
        float4 v = *(const float4*)(fp + c0 + 128);
        a.x = fmaxf(a.x, u.x); a.y = fmaxf(a.y, u.y);
        a.z = fmaxf(a.z, u.z); a.w = fmaxf(a.w, u.w);
        bq.x = fmaxf(bq.x, v.x); bq.y = fmaxf(bq.y, v.y);
        bq.z = fmaxf(bq.z, v.z); bq.w = fmaxf(bq.w, v.w);
    }
    const float4 ba = *(const float4*)(bias + c0);
    const float4 bb = *(const float4*)(bias + c0 + 128);
    a.x += ba.x; a.y += ba.y; a.z += ba.z; a.w += ba.w;
    bq.x += bb.x; bq.y += bb.y; bq.z += bb.z; bq.w += bb.w;
    *(float4*)(op + c0) = a;
    *(float4*)(op + c0 + 128) = bq;
}

// ------------------------------- launch ------------------------------------
extern "C" void kernel_launch(void* const* d_in, const int* in_sizes, int n_in,
                              void* d_out, int out_size){
    const float* hh = (const float*)d_in[0];
    const float* sl = (const float*)d_in[1];
    const float* sc = (const float*)d_in[2];
    const float* W  = (const float*)d_in[3];
    const float* bb = (const float*)d_in[4];
    (void)in_sizes; (void)n_in;

    cudaFuncSetAttribute(k_gemm_tc, cudaFuncAttributeMaxDynamicSharedMemorySize, SMEM_G);

    k_wsplit<<<(KP_*H_ + 255)/256, 256>>>(W);
    k_select<<<B_, 1024>>>(sc, (float*)d_out, (long long)out_size);
    dim3 gknn(ND_ / 512, B_);
    k_knn<<<gknn, 256>>>(sl);
    k_scan<<<B_, 1024>>>();
    k_fill<<<(B_*ND_*M_ + 255)/256, 256>>>();
    dim3 gg(ND_ / BM2, B_);
    k_gemm_tc<<<gg, 256, SMEM_G>>>(hh, sl, sc);
    k_gather<<<B_*N_/8, 256>>>((float*)d_out, bb);
}

// round 6
// speedup vs baseline: 1.7264x; 1.0088x over previous
#include <cuda_runtime.h>
#include <cuda_bf16.h>
#include <mma.h>
#include <cstdint>

using namespace nvcuda;

#define B_  8
#define N_  8192
#define H_  256
#define KD_ 260            // H + 4
#define KP_ 288            // K padded to 9*32
#define NU_ 2048
#define ND_ 6144
#define M_  5
#define EPG (ND_*M_)       // edges per graph = 30720
#define BM2 64             // GEMM M tile
#define BN2 256            // GEMM N tile (= H, one tile)
#define LDA2 40
#define LDB2 264
// dynamic smem byte offsets (2-stage pipeline)
#define OFF_AHI(s) ((s)*5120)
#define OFF_ALO(s) (10240 + (s)*5120)
#define OFF_BHI(s) (20480 + (s)*16896)
#define OFF_BLO(s) (54272 + (s)*16896)
#define SMEM_G 88064

// ---------------- device scratch ----------------
__device__ int  g_up_idx[B_*NU_];
__device__ int  g_down_idx[B_*ND_];
__device__ int  g_dst[B_*ND_*M_];
__device__ unsigned char g_isup[B_*N_];
__device__ int  g_deg[B_*N_];
__device__ int  g_off[B_*N_];
__device__ int  g_cur[B_*N_];
__device__ int  g_src[B_*ND_*M_];
__device__ float g_feat[(size_t)B_*ND_*H_];
__device__ __nv_bfloat16 g_Whi[KP_*H_];
__device__ __nv_bfloat16 g_Wlo[KP_*H_];

__device__ __forceinline__ unsigned enc_f(float f){
    unsigned u = __float_as_uint(f);
    return (u & 0x80000000u) ? ~u : (u | 0x80000000u);
}
__device__ __forceinline__ void cpa16(void* dst, const void* src){
    unsigned d = (unsigned)__cvta_generic_to_shared(dst);
    asm volatile("cp.async.cg.shared.global [%0], [%1], 16;" :: "r"(d), "l"(src));
}

// shuffle-based exclusive block scan (1024 threads, 2 barriers)
__device__ __forceinline__ int block_scan_excl(int val, int* s_warp, int tid){
    const int lane = tid & 31, wid = tid >> 5;
    int inc = val;
#pragma unroll
    for (int o = 1; o < 32; o <<= 1){
        int v = __shfl_up_sync(0xFFFFFFFFu, inc, o);
        if (lane >= o) inc += v;
    }
    if (lane == 31) s_warp[wid] = inc;
    __syncthreads();
    if (wid == 0){
        int w = (lane < 32) ? s_warp[lane] : 0;
#pragma unroll
        for (int o = 1; o < 32; o <<= 1){
            int v = __shfl_up_sync(0xFFFFFFFFu, w, o);
            if (lane >= o) w += v;
        }
        s_warp[lane] = w;
    }
    __syncthreads();
    int base = (wid > 0) ? s_warp[wid - 1] : 0;
    return base + inc - val;
}

// ---------------- K0: W split into hi/lo bf16 ----------------
__global__ void k_wsplit(const float* __restrict__ W){
    const int idx = blockIdx.x * 256 + threadIdx.x;
    if (idx >= KP_ * H_) return;
    const int k = idx / H_, n = idx % H_;
    const float w = (k < KD_) ? W[k * H_ + n] : 0.0f;
    const __nv_bfloat16 hi = __float2bfloat16(w);
    const __nv_bfloat16 lo = __float2bfloat16(w - __bfloat162float(hi));
    g_Whi[idx] = hi;
    g_Wlo[idx] = lo;
}

// ---------------- K1: top-25% selection (8-bit radix, 256 bins) ------------
__global__ void k_select(const float* __restrict__ scores,
                         float* __restrict__ d_out, long long out_size){
    __shared__ unsigned s_enc[N_];
    __shared__ int s_warp[32];
    __shared__ int s_hist[256];
    __shared__ int s_bcast[2];
    const int b = blockIdx.x, tid = threadIdx.x;

    for (int i = tid; i < N_; i += 1024) g_deg[b * N_ + i] = 0;

    const float* sc = scores + (long long)b * N_;
    for (int i = tid; i < N_; i += 1024) s_enc[i] = enc_f(sc[i]);
    __syncthreads();

    unsigned prefix = 0, known = 0;
    int k = NU_;
    for (int lvl = 3; lvl >= 0; --lvl){
        if (tid < 256) s_hist[tid] = 0;
        __syncthreads();
        const int sh = lvl * 8;
        for (int i = tid; i < N_; i += 1024){
            unsigned e = s_enc[i];
            if ((e & known) == prefix) atomicAdd(&s_hist[(e >> sh) & 255], 1);
        }
        __syncthreads();
        if (tid == 0){
            int kk = k, bin = 255;
            while (bin > 0 && kk > s_hist[bin]) { kk -= s_hist[bin]; --bin; }
            s_bcast[0] = bin; s_bcast[1] = kk;
        }
        __syncthreads();
        prefix |= ((unsigned)s_bcast[0]) << sh;
        known  |= 0xFFu << sh;
        k = s_bcast[1];
        __syncthreads();
    }
    const unsigned T = prefix;

    if (tid == 0) s_bcast[0] = 0;
    __syncthreads();
    {
        int loc = 0;
        for (int i = tid; i < N_; i += 1024) if (s_enc[i] > T) loc++;
        atomicAdd(&s_bcast[0], loc);
    }
    __syncthreads();
    const int need_eq = NU_ - s_bcast[0];
    __syncthreads();

    const int base = tid * 8;
    int eqc = 0;
#pragma unroll
    for (int e = 0; e < 8; ++e) eqc += (s_enc[base + e] == T);
    int eqbase = block_scan_excl(eqc, s_warp, tid);
    __syncthreads();

    unsigned mbits = 0; int upc = 0;
    {
        int ec = eqbase;
#pragma unroll
        for (int e = 0; e < 8; ++e){
            unsigned v = s_enc[base + e];
            bool msk;
            if (v > T) msk = true;
            else if (v == T) { msk = (ec < need_eq); ec++; }
            else msk = false;
            if (msk) { mbits |= (1u << e); upc++; }
        }
    }
    int upbase = block_scan_excl(upc, s_warp, tid);

    const long long BNH = (long long)B_ * N_ * H_;
    const bool wf = (out_size == BNH + (long long)B_ * N_);
    const bool wb = (out_size == BNH + ((long long)B_ * N_) / 4);
    int up = upbase;
#pragma unroll
    for (int e = 0; e < 8; ++e){
        const int i = base + e;
        const bool msk = (mbits >> e) & 1;
        if (msk) { g_up_idx[b * NU_ + up] = i; up++; }
        else       g_down_idx[b * ND_ + (i - up)] = i;
        g_isup[b * N_ + i] = msk ? 1 : 0;
        if (wf)      d_out[BNH + (long long)b * N_ + i] = msk ? 1.0f : 0.0f;
        else if (wb) ((unsigned char*)d_out)[BNH * 4 + (long long)b * N_ + i] = msk ? 1 : 0;
    }
}

// -------- K2: directional 5-NN + degree count --------
struct Top5 { float d0,d1,d2,d3,d4; int i0,i1,i2,i3,i4; };
__device__ __forceinline__ void top5_init(Top5& t){
    const float INF = __int_as_float(0x7f800000);
    t.d0=t.d1=t.d2=t.d3=t.d4=INF; t.i0=t.i1=t.i2=t.i3=t.i4=0;
}
__device__ __forceinline__ void top5_ins(Top5& t, float d, int j){
    if (d < t.d4){
        if (d < t.d3){ t.d4=t.d3; t.i4=t.i3;
            if (d < t.d2){ t.d3=t.d2; t.i3=t.i2;
                if (d < t.d1){ t.d2=t.d1; t.i2=t.i1;
                    if (d < t.d0){ t.d1=t.d0; t.i1=t.i0; t.d0=d; t.i0=j; }
                    else        { t.d1=d;  t.i1=j; }
                } else { t.d2=d; t.i2=j; }
            } else { t.d3=d; t.i3=j; }
        } else { t.d4=d; t.i4=j; }
    }
}

__global__ void k_knn(const float* __restrict__ s_l){
    __shared__ float4 su[NU_];
    const int b = blockIdx.y;
    const int tid = threadIdx.x;
    for (int j = tid; j < NU_; j += 256){
        int u = g_up_idx[b * NU_ + j];
        long long p = ((long long)b * N_ + u) * 3;
        su[j] = make_float4(s_l[p], s_l[p+1], s_l[p+2], __int_as_float(b * N_ + u));
    }
    __syncthreads();

    const int dlA = blockIdx.x * 512 + tid;
    const int dlB = dlA + 256;
    const int dnA = g_down_idx[b * ND_ + dlA];
    const int dnB = g_down_idx[b * ND_ + dlB];
    long long pA = ((long long)b * N_ + dnA) * 3;
    long long pB = ((long long)b * N_ + dnB) * 3;
    const float xA = s_l[pA], yA = s_l[pA+1], zA = s_l[pA+2];
    const float xB = s_l[pB], yB = s_l[pB+1], zB = s_l[pB+2];

    Top5 tA, tB; top5_init(tA); top5_init(tB);
    for (int j = 0; j < NU_; ++j){
        const float4 u = su[j];
        float dxA = xA-u.x, dyA = yA-u.y, dzA = zA-u.z;
        float dxB = xB-u.x, dyB = yB-u.y, dzB = zB-u.z;
        float dA = dxA*dxA + dyA*dyA + dzA*dzA;
        float dB = dxB*dxB + dyB*dyB + dzB*dzB;
        top5_ins(tA, dA, j);
        top5_ins(tB, dB, j);
    }
    {
        int* dst = g_dst + ((long long)b * ND_ + dlA) * M_;
        int e0=__float_as_int(su[tA.i0].w), e1=__float_as_int(su[tA.i1].w),
            e2=__float_as_int(su[tA.i2].w), e3=__float_as_int(su[tA.i3].w),
            e4=__float_as_int(su[tA.i4].w);
        dst[0]=e0; dst[1]=e1; dst[2]=e2; dst[3]=e3; dst[4]=e4;
        atomicAdd(&g_deg[e0],1); atomicAdd(&g_deg[e1],1); atomicAdd(&g_deg[e2],1);
        atomicAdd(&g_deg[e3],1); atomicAdd(&g_deg[e4],1);
    }
    {
        int* dst = g_dst + ((long long)b * ND_ + dlB) * M_;
        int e0=__float_as_int(su[tB.i0].w), e1=__float_as_int(su[tB.i1].w),
            e2=__float_as_int(su[tB.i2].w), e3=__float_as_int(su[tB.i3].w),
            e4=__float_as_int(su[tB.i4].w);
        dst[0]=e0; dst[1]=e1; dst[2]=e2; dst[3]=e3; dst[4]=e4;
        atomicAdd(&g_deg[e0],1); atomicAdd(&g_deg[e1],1); atomicAdd(&g_deg[e2],1);
        atomicAdd(&g_deg[e3],1); atomicAdd(&g_deg[e4],1);
    }
}

// -------- K3: per-graph exclusive scan --------
__global__ void k_scan(){
    __shared__ int s_warp[32];
    const int b = blockIdx.x, tid = threadIdx.x;
    const int base = b * N_ + tid * 8;
    int d[8]; int s = 0;
#pragma unroll
    for (int i = 0; i < 8; ++i){ d[i] = g_deg[base + i]; s += d[i]; }
    int run = block_scan_excl(s, s_warp, tid) + b * EPG;
#pragma unroll
    for (int i = 0; i < 8; ++i){
        g_off[base + i] = run;
        g_cur[base + i] = run;
        run += d[i];
    }
}

// ---------------- K4: CSR fill ----------------
__global__ void k_fill(){
    const int e = blockIdx.x * 256 + threadIdx.x;
    if (e >= B_ * ND_ * M_) return;
    const int dst = g_dst[e];
    const int pos = atomicAdd(&g_cur[dst], 1);
    g_src[pos] = e / M_;
}

// -------- K5: pipelined WMMA bf16 hi/lo GEMM, BM=64 x BN=256 --------
__device__ __forceinline__ void loadA_regs(float* xs, const float* __restrict__ hh,
                                           const float* __restrict__ sl,
                                           const float* __restrict__ sc,
                                           int g, int c, int ah){
    if (c < 8){
        const float4* hp = (const float4*)(hh + (size_t)g * H_ + c * 32 + ah);
        float4 f0 = hp[0], f1 = hp[1];
        xs[0]=f0.x; xs[1]=f0.y; xs[2]=f0.z; xs[3]=f0.w;
        xs[4]=f1.x; xs[5]=f1.y; xs[6]=f1.z; xs[7]=f1.w;
    } else {
#pragma unroll
        for (int q = 0; q < 8; ++q) xs[q] = 0.0f;
        if (ah == 0){
            xs[0] = sl[(size_t)g * 3];
            xs[1] = sl[(size_t)g * 3 + 1];
            xs[2] = sl[(size_t)g * 3 + 2];
            xs[3] = sc[g];
        }
    }
}

__global__ void __launch_bounds__(256)
k_gemm_tc(const float* __restrict__ hh, const float* __restrict__ sl,
          const float* __restrict__ sc){
    extern __shared__ char sm[];
    __shared__ int s_g[BM2];

    const int b   = blockIdx.y;
    const int m0  = blockIdx.x * BM2;
    const int tid = threadIdx.x;
    const int w   = tid >> 5;
    const int wm  = w >> 2;
    const int wn  = w & 3;

    if (tid < BM2) s_g[tid] = b * N_ + g_down_idx[b * ND_ + m0 + tid];
    __syncthreads();

    const int ar = tid >> 2;
    const int ah = (tid & 3) * 8;
    const int g  = s_g[ar];

    wmma::fragment<wmma::accumulator, 16, 16, 16, float> acc[2][4];
#pragma unroll
    for (int i = 0; i < 2; ++i)
#pragma unroll
        for (int j = 0; j < 4; ++j) wmma::fill_fragment(acc[i][j], 0.0f);

    auto copyB = [&](int c, int s){
        const int k0 = c * 32;
        __nv_bfloat16* Bh = (__nv_bfloat16*)(sm + OFF_BHI(s));
        __nv_bfloat16* Bl = (__nv_bfloat16*)(sm + OFF_BLO(s));
#pragma unroll
        for (int q = 0; q < 4; ++q){
            const int i = tid + q * 256;
            const int row = i >> 5;
            const int col = (i & 31) * 8;
            cpa16(Bh + row * LDB2 + col, g_Whi + (size_t)(k0 + row) * H_ + col);
            cpa16(Bl + row * LDB2 + col, g_Wlo + (size_t)(k0 + row) * H_ + col);
        }
        asm volatile("cp.async.commit_group;");
    };
    auto storeA = [&](const float* xs, int s){
        unsigned hw[4], lw[4];
#pragma unroll
        for (int q = 0; q < 4; ++q){
            __nv_bfloat16 h0 = __float2bfloat16(xs[2*q]);
            __nv_bfloat16 h1 = __float2bfloat16(xs[2*q+1]);
            __nv_bfloat16 l0 = __float2bfloat16(xs[2*q]   - __bfloat162float(h0));
            __nv_bfloat16 l1 = __float2bfloat16(xs[2*q+1] - __bfloat162float(h1));
            __nv_bfloat162 hp2 = __nv_bfloat162(h0, h1);
            __nv_bfloat162 lp2 = __nv_bfloat162(l0, l1);
            hw[q] = *(unsigned*)&hp2;
            lw[q] = *(unsigned*)&lp2;
        }
        *(uint4*)((__nv_bfloat16*)(sm + OFF_AHI(s)) + ar * LDA2 + ah) =
            make_uint4(hw[0], hw[1], hw[2], hw[3]);
        *(uint4*)((__nv_bfloat16*)(sm + OFF_ALO(s)) + ar * LDA2 + ah) =
            make_uint4(lw[0], lw[1], lw[2], lw[3]);
    };

    float xs[8], xs2[8];
    loadA_regs(xs, hh, sl, sc, g, 0, ah);
    copyB(0, 0);

    for (int c = 0; c < 9; ++c){
        const int s = c & 1;
        if (c < 8){
            loadA_regs(xs2, hh, sl, sc, g, c + 1, ah);
            copyB(c + 1, s ^ 1);
        }
        storeA(xs, s);
        if (c < 8) asm volatile("cp.async.wait_group 1;");
        else       asm volatile("cp.async.wait_group 0;");
        __syncthreads();

        const __nv_bfloat16* Ah = (const __nv_bfloat16*)(sm + OFF_AHI(s));
        const __nv_bfloat16* Al = (const __nv_bfloat16*)(sm + OFF_ALO(s));
        const __nv_bfloat16* Bh = (const __nv_bfloat16*)(sm + OFF_BHI(s));
        const __nv_bfloat16* Bl = (const __nv_bfloat16*)(sm + OFF_BLO(s));
#pragma unroll
        for (int kt = 0; kt < 2; ++kt){
            const int ks = kt * 16;
            wmma::fragment<wmma::matrix_a, 16, 16, 16, __nv_bfloat16, wmma::row_major> fa_hi[2], fa_lo[2];
#pragma unroll
            for (int i = 0; i < 2; ++i){
                wmma::load_matrix_sync(fa_hi[i], Ah + (wm*32 + i*16) * LDA2 + ks, LDA2);
                wmma::load_matrix_sync(fa_lo[i], Al + (wm*32 + i*16) * LDA2 + ks, LDA2);
            }
#pragma unroll
            for (int j = 0; j < 4; ++j){
                wmma::fragment<wmma::matrix_b, 16, 16, 16, __nv_bfloat16, wmma::row_major> fb_hi, fb_lo;
                wmma::load_matrix_sync(fb_hi, Bh + ks * LDB2 + wn*64 + j*16, LDB2);
                wmma::load_matrix_sync(fb_lo, Bl + ks * LDB2 + wn*64 + j*16, LDB2);
#pragma unroll
                for (int i = 0; i < 2; ++i){
                    wmma::mma_sync(acc[i][j], fa_hi[i], fb_hi, acc[i][j]);
                    wmma::mma_sync(acc[i][j], fa_hi[i], fb_lo, acc[i][j]);
                    wmma::mma_sync(acc[i][j], fa_lo[i], fb_hi, acc[i][j]);
                }
            }
        }
        __syncthreads();
#pragma unroll
        for (int q = 0; q < 8; ++q) xs[q] = xs2[q];
    }

#pragma unroll
    for (int i = 0; i < 2; ++i){
        const int row = m0 + wm * 32 + i * 16;
#pragma unroll
        for (int j = 0; j < 4; ++j){
            const int col = wn * 64 + j * 16;
            wmma::store_matrix_sync(
                g_feat + ((size_t)b * ND_ + row) * H_ + col,
                acc[i][j], H_, wmma::mem_row_major);
        }
    }
}

// ---------------- K6: gather-max (+bias) into output ----------------
__global__ void k_gather(float* __restrict__ out, const float* __restrict__ bias){
    const int wid = threadIdx.x >> 5, lane = threadIdx.x & 31;
    const int row = blockIdx.x * 8 + wid;
    float* op = out + (size_t)row * H_;
    const int c0 = lane * 4;
    const float4 z = make_float4(0.f, 0.f, 0.f, 0.f);
    const int deg = g_deg[row];
    if (!g_isup[row] || deg == 0){
        *(float4*)(op + c0) = z;
        *(float4*)(op + c0 + 128) = z;
        return;
    }
    const int off = g_off[row];
    const float NI = __int_as_float(0xff800000);
    float4 a = make_float4(NI, NI, NI, NI), bq = a;
    for (int e = 0; e < deg; ++e){
        const float* fp = g_feat + (size_t)g_src[off + e] * H_;
        float4 u = *(const float4*)(fp + c0);
        float4 v = *(const float4*)(fp + c0 + 128);
        a.x = fmaxf(a.x, u.x); a.y = fmaxf(a.y, u.y);
        a.z = fmaxf(a.z, u.z); a.w = fmaxf(a.w, u.w);
        bq.x = fmaxf(bq.x, v.x); bq.y = fmaxf(bq.y, v.y);
        bq.z = fmaxf(bq.z, v.z); bq.w = fmaxf(bq.w, v.w);
    }
    const float4 ba = *(const float4*)(bias + c0);
    const float4 bb = *(const float4*)(bias + c0 + 128);
    a.x += ba.x; a.y += ba.y; a.z += ba.z; a.w += ba.w;
    bq.x += bb.x; bq.y += bb.y; bq.z += bb.z; bq.w += bb.w;
    *(float4*)(op + c0) = a;
    *(float4*)(op + c0 + 128) = bq;
}

// ------------------------------- launch ------------------------------------
extern "C" void kernel_launch(void* const* d_in, const int* in_sizes, int n_in,
                              void* d_out, int out_size){
    const float* hh = (const float*)d_in[0];
    const float* sl = (const float*)d_in[1];
    const float* sc = (const float*)d_in[2];
    const float* W  = (const float*)d_in[3];
    const float* bb = (const float*)d_in[4];
    (void)in_sizes; (void)n_in;

    cudaFuncSetAttribute(k_gemm_tc, cudaFuncAttributeMaxDynamicSharedMemorySize, SMEM_G);

    // NOTE: k_gemm_tc only needs g_down_idx (from k_select); moved to slot 3
    // so the fixed ncu window (-s 5 -c 1) profiles it this round.
    k_wsplit<<<(KP_*H_ + 255)/256, 256>>>(W);                 // slot 0
    k_select<<<B_, 1024>>>(sc, (float*)d_out, (long long)out_size); // slot 1
    dim3 gknn(ND_ / 512, B_);
    k_knn<<<gknn, 256>>>(sl);                                  // slot 2
    dim3 gg(ND_ / BM2, B_);
    k_gemm_tc<<<gg, 256, SMEM_G>>>(hh, sl, sc);               // slot 3 (profiled)
    k_scan<<<B_, 1024>>>();                                    // slot 4
    k_fill<<<(B_*ND_*M_ + 255)/256, 256>>>();                  // slot 5
    k_gather<<<B_*N_/8, 256>>>((float*)d_out, bb);             // slot 6
}

// round 7
// speedup vs baseline: 1.8343x; 1.0625x over previous
#include <cuda_runtime.h>
#include <cuda_bf16.h>
#include <mma.h>
#include <cstdint>

using namespace nvcuda;

#define B_  8
#define N_  8192
#define H_  256
#define KD_ 260            // H + 4
#define KP_ 288            // K padded to 9*32
#define NU_ 2048
#define ND_ 6144
#define M_  5
#define EPG (ND_*M_)       // edges per graph = 30720
#define BM2 128            // GEMM M tile
#define BN2 256            // GEMM N tile (= H, one tile)
#define GT_ 512            // GEMM threads
#define LDA2 40
#define LDB2 264
// dynamic smem byte offsets (2-stage pipeline)
#define GA_HI(s) ((s)*10240)
#define GA_LO(s) (20480 + (s)*10240)
#define GB_HI(s) (40960 + (s)*16896)
#define GB_LO(s) (74752 + (s)*16896)
#define SMEM_G 108544

// ---------------- device scratch ----------------
__device__ int  g_up_idx[B_*NU_];
__device__ int  g_down_idx[B_*ND_];
__device__ int  g_dst[B_*ND_*M_];
__device__ unsigned char g_isup[B_*N_];
__device__ int  g_deg[B_*N_];
__device__ int  g_off[B_*N_];
__device__ int  g_cur[B_*N_];
__device__ int  g_src[B_*ND_*M_];
__device__ float g_feat[(size_t)B_*ND_*H_];
__device__ __nv_bfloat16 g_Whi[KP_*H_];
__device__ __nv_bfloat16 g_Wlo[KP_*H_];

__device__ __forceinline__ unsigned enc_f(float f){
    unsigned u = __float_as_uint(f);
    return (u & 0x80000000u) ? ~u : (u | 0x80000000u);
}
__device__ __forceinline__ void cpa16(void* dst, const void* src){
    unsigned d = (unsigned)__cvta_generic_to_shared(dst);
    asm volatile("cp.async.cg.shared.global [%0], [%1], 16;" :: "r"(d), "l"(src));
}

// shuffle-based exclusive block scan (1024 threads, 2 barriers)
__device__ __forceinline__ int block_scan_excl(int val, int* s_warp, int tid){
    const int lane = tid & 31, wid = tid >> 5;
    int inc = val;
#pragma unroll
    for (int o = 1; o < 32; o <<= 1){
        int v = __shfl_up_sync(0xFFFFFFFFu, inc, o);
        if (lane >= o) inc += v;
    }
    if (lane == 31) s_warp[wid] = inc;
    __syncthreads();
    if (wid == 0){
        int w = (lane < 32) ? s_warp[lane] : 0;
#pragma unroll
        for (int o = 1; o < 32; o <<= 1){
            int v = __shfl_up_sync(0xFFFFFFFFu, w, o);
            if (lane >= o) w += v;
        }
        s_warp[lane] = w;
    }
    __syncthreads();
    int base = (wid > 0) ? s_warp[wid - 1] : 0;
    return base + inc - val;
}

// ---------------- K0: W split into hi/lo bf16 ----------------
__global__ void k_wsplit(const float* __restrict__ W){
    const int idx = blockIdx.x * 256 + threadIdx.x;
    if (idx >= KP_ * H_) return;
    const int k = idx / H_, n = idx % H_;
    const float w = (k < KD_) ? W[k * H_ + n] : 0.0f;
    const __nv_bfloat16 hi = __float2bfloat16(w);
    const __nv_bfloat16 lo = __float2bfloat16(w - __bfloat162float(hi));
    g_Whi[idx] = hi;
    g_Wlo[idx] = lo;
}

// ---------------- K1: top-25% selection (8-bit radix, 256 bins) ------------
__global__ void k_select(const float* __restrict__ scores,
                         float* __restrict__ d_out, long long out_size){
    __shared__ unsigned s_enc[N_];
    __shared__ int s_warp[32];
    __shared__ int s_hist[256];
    __shared__ int s_bcast[2];
    const int b = blockIdx.x, tid = threadIdx.x;

    for (int i = tid; i < N_; i += 1024) g_deg[b * N_ + i] = 0;

    const float* sc = scores + (long long)b * N_;
    for (int i = tid; i < N_; i += 1024) s_enc[i] = enc_f(sc[i]);
    __syncthreads();

    unsigned prefix = 0, known = 0;
    int k = NU_;
    for (int lvl = 3; lvl >= 0; --lvl){
        if (tid < 256) s_hist[tid] = 0;
        __syncthreads();
        const int sh = lvl * 8;
        for (int i = tid; i < N_; i += 1024){
            unsigned e = s_enc[i];
            if ((e & known) == prefix) atomicAdd(&s_hist[(e >> sh) & 255], 1);
        }
        __syncthreads();
        if (tid == 0){
            int kk = k, bin = 255;
            while (bin > 0 && kk > s_hist[bin]) { kk -= s_hist[bin]; --bin; }
            s_bcast[0] = bin; s_bcast[1] = kk;
        }
        __syncthreads();
        prefix |= ((unsigned)s_bcast[0]) << sh;
        known  |= 0xFFu << sh;
        k = s_bcast[1];
        __syncthreads();
    }
    const unsigned T = prefix;

    if (tid == 0) s_bcast[0] = 0;
    __syncthreads();
    {
        int loc = 0;
        for (int i = tid; i < N_; i += 1024) if (s_enc[i] > T) loc++;
        atomicAdd(&s_bcast[0], loc);
    }
    __syncthreads();
    const int need_eq = NU_ - s_bcast[0];
    __syncthreads();

    const int base = tid * 8;
    int eqc = 0;
#pragma unroll
    for (int e = 0; e < 8; ++e) eqc += (s_enc[base + e] == T);
    int eqbase = block_scan_excl(eqc, s_warp, tid);
    __syncthreads();

    unsigned mbits = 0; int upc = 0;
    {
        int ec = eqbase;
#pragma unroll
        for (int e = 0; e < 8; ++e){
            unsigned v = s_enc[base + e];
            bool msk;
            if (v > T) msk = true;
            else if (v == T) { msk = (ec < need_eq); ec++; }
            else msk = false;
            if (msk) { mbits |= (1u << e); upc++; }
        }
    }
    int upbase = block_scan_excl(upc, s_warp, tid);

    const long long BNH = (long long)B_ * N_ * H_;
    const bool wf = (out_size == BNH + (long long)B_ * N_);
    const bool wb = (out_size == BNH + ((long long)B_ * N_) / 4);
    int up = upbase;
#pragma unroll
    for (int e = 0; e < 8; ++e){
        const int i = base + e;
        const bool msk = (mbits >> e) & 1;
        if (msk) { g_up_idx[b * NU_ + up] = i; up++; }
        else       g_down_idx[b * ND_ + (i - up)] = i;
        g_isup[b * N_ + i] = msk ? 1 : 0;
        if (wf)      d_out[BNH + (long long)b * N_ + i] = msk ? 1.0f : 0.0f;
        else if (wb) ((unsigned char*)d_out)[BNH * 4 + (long long)b * N_ + i] = msk ? 1 : 0;
    }
}

// -------- K2: directional 5-NN + degree count --------
struct Top5 { float d0,d1,d2,d3,d4; int i0,i1,i2,i3,i4; };
__device__ __forceinline__ void top5_init(Top5& t){
    const float INF = __int_as_float(0x7f800000);
    t.d0=t.d1=t.d2=t.d3=t.d4=INF; t.i0=t.i1=t.i2=t.i3=t.i4=0;
}
__device__ __forceinline__ void top5_ins(Top5& t, float d, int j){
    if (d < t.d4){
        if (d < t.d3){ t.d4=t.d3; t.i4=t.i3;
            if (d < t.d2){ t.d3=t.d2; t.i3=t.i2;
                if (d < t.d1){ t.d2=t.d1; t.i2=t.i1;
                    if (d < t.d0){ t.d1=t.d0; t.i1=t.i0; t.d0=d; t.i0=j; }
                    else        { t.d1=d;  t.i1=j; }
                } else { t.d2=d; t.i2=j; }
            } else { t.d3=d; t.i3=j; }
        } else { t.d4=d; t.i4=j; }
    }
}

__global__ void k_knn(const float* __restrict__ s_l){
    __shared__ float4 su[NU_];
    const int b = blockIdx.y;
    const int tid = threadIdx.x;
    for (int j = tid; j < NU_; j += 256){
        int u = g_up_idx[b * NU_ + j];
        long long p = ((long long)b * N_ + u) * 3;
        su[j] = make_float4(s_l[p], s_l[p+1], s_l[p+2], __int_as_float(b * N_ + u));
    }
    __syncthreads();

    const int dlA = blockIdx.x * 512 + tid;
    const int dlB = dlA + 256;
    const int dnA = g_down_idx[b * ND_ + dlA];
    const int dnB = g_down_idx[b * ND_ + dlB];
    long long pA = ((long long)b * N_ + dnA) * 3;
    long long pB = ((long long)b * N_ + dnB) * 3;
    const float xA = s_l[pA], yA = s_l[pA+1], zA = s_l[pA+2];
    const float xB = s_l[pB], yB = s_l[pB+1], zB = s_l[pB+2];

    Top5 tA, tB; top5_init(tA); top5_init(tB);
    for (int j = 0; j < NU_; ++j){
        const float4 u = su[j];
        float dxA = xA-u.x, dyA = yA-u.y, dzA = zA-u.z;
        float dxB = xB-u.x, dyB = yB-u.y, dzB = zB-u.z;
        float dA = dxA*dxA + dyA*dyA + dzA*dzA;
        float dB = dxB*dxB + dyB*dyB + dzB*dzB;
        top5_ins(tA, dA, j);
        top5_ins(tB, dB, j);
    }
    {
        int* dst = g_dst + ((long long)b * ND_ + dlA) * M_;
        int e0=__float_as_int(su[tA.i0].w), e1=__float_as_int(su[tA.i1].w),
            e2=__float_as_int(su[tA.i2].w), e3=__float_as_int(su[tA.i3].w),
            e4=__float_as_int(su[tA.i4].w);
        dst[0]=e0; dst[1]=e1; dst[2]=e2; dst[3]=e3; dst[4]=e4;
        atomicAdd(&g_deg[e0],1); atomicAdd(&g_deg[e1],1); atomicAdd(&g_deg[e2],1);
        atomicAdd(&g_deg[e3],1); atomicAdd(&g_deg[e4],1);
    }
    {
        int* dst = g_dst + ((long long)b * ND_ + dlB) * M_;
        int e0=__float_as_int(su[tB.i0].w), e1=__float_as_int(su[tB.i1].w),
            e2=__float_as_int(su[tB.i2].w), e3=__float_as_int(su[tB.i3].w),
            e4=__float_as_int(su[tB.i4].w);
        dst[0]=e0; dst[1]=e1; dst[2]=e2; dst[3]=e3; dst[4]=e4;
        atomicAdd(&g_deg[e0],1); atomicAdd(&g_deg[e1],1); atomicAdd(&g_deg[e2],1);
        atomicAdd(&g_deg[e3],1); atomicAdd(&g_deg[e4],1);
    }
}

// -------- K3: per-graph exclusive scan --------
__global__ void k_scan(){
    __shared__ int s_warp[32];
    const int b = blockIdx.x, tid = threadIdx.x;
    const int base = b * N_ + tid * 8;
    int d[8]; int s = 0;
#pragma unroll
    for (int i = 0; i < 8; ++i){ d[i] = g_deg[base + i]; s += d[i]; }
    int run = block_scan_excl(s, s_warp, tid) + b * EPG;
#pragma unroll
    for (int i = 0; i < 8; ++i){
        g_off[base + i] = run;
        g_cur[base + i] = run;
        run += d[i];
    }
}

// ---------------- K4: CSR fill ----------------
__global__ void k_fill(){
    const int e = blockIdx.x * 256 + threadIdx.x;
    if (e >= B_ * ND_ * M_) return;
    const int dst = g_dst[e];
    const int pos = atomicAdd(&g_cur[dst], 1);
    g_src[pos] = e / M_;
}

// -------- K5: pipelined WMMA bf16 hi/lo GEMM, BM=128 x BN=256, 512 thr ------
__device__ __forceinline__ void loadA_regs(float* xs, const float* __restrict__ hh,
                                           const float* __restrict__ sl,
                                           const float* __restrict__ sc,
                                           int g, int c, int ah){
    if (c < 8){
        const float4* hp = (const float4*)(hh + (size_t)g * H_ + c * 32 + ah);
        float4 f0 = hp[0], f1 = hp[1];
        xs[0]=f0.x; xs[1]=f0.y; xs[2]=f0.z; xs[3]=f0.w;
        xs[4]=f1.x; xs[5]=f1.y; xs[6]=f1.z; xs[7]=f1.w;
    } else {
#pragma unroll
        for (int q = 0; q < 8; ++q) xs[q] = 0.0f;
        if (ah == 0){
            xs[0] = sl[(size_t)g * 3];
            xs[1] = sl[(size_t)g * 3 + 1];
            xs[2] = sl[(size_t)g * 3 + 2];
            xs[3] = sc[g];
        }
    }
}

__global__ void __launch_bounds__(GT_, 1)
k_gemm_tc(const float* __restrict__ hh, const float* __restrict__ sl,
          const float* __restrict__ sc){
    extern __shared__ char sm[];
    __shared__ int s_g[BM2];

    const int b   = blockIdx.y;
    const int m0  = blockIdx.x * BM2;
    const int tid = threadIdx.x;
    const int w   = tid >> 5;
    const int wm  = w >> 2;          // 0..3 -> rows wm*32
    const int wn  = w & 3;           // 0..3 -> cols wn*64

    if (tid < BM2) s_g[tid] = b * N_ + g_down_idx[b * ND_ + m0 + tid];
    __syncthreads();

    const int ar = tid >> 2;         // 0..127
    const int ah = (tid & 3) * 8;    // 0,8,16,24
    const int g  = s_g[ar];

    wmma::fragment<wmma::accumulator, 16, 16, 16, float> acc[2][4];
#pragma unroll
    for (int i = 0; i < 2; ++i)
#pragma unroll
        for (int j = 0; j < 4; ++j) wmma::fill_fragment(acc[i][j], 0.0f);

    // B copy: 1024 16B-chunks per matrix, 2 per thread
    auto copyB = [&](int c, int s){
        const int k0 = c * 32;
        __nv_bfloat16* Bh = (__nv_bfloat16*)(sm + GB_HI(s));
        __nv_bfloat16* Bl = (__nv_bfloat16*)(sm + GB_LO(s));
#pragma unroll
        for (int q = 0; q < 2; ++q){
            const int i = tid + q * GT_;
            const int row = i >> 5;
            const int col = (i & 31) * 8;
            cpa16(Bh + row * LDB2 + col, g_Whi + (size_t)(k0 + row) * H_ + col);
            cpa16(Bl + row * LDB2 + col, g_Wlo + (size_t)(k0 + row) * H_ + col);
        }
        asm volatile("cp.async.commit_group;");
    };
    auto storeA = [&](const float* xs, int s){
        unsigned hw[4], lw[4];
#pragma unroll
        for (int q = 0; q < 4; ++q){
            __nv_bfloat16 h0 = __float2bfloat16(xs[2*q]);
            __nv_bfloat16 h1 = __float2bfloat16(xs[2*q+1]);
            __nv_bfloat16 l0 = __float2bfloat16(xs[2*q]   - __bfloat162float(h0));
            __nv_bfloat16 l1 = __float2bfloat16(xs[2*q+1] - __bfloat162float(h1));
            __nv_bfloat162 hp2 = __nv_bfloat162(h0, h1);
            __nv_bfloat162 lp2 = __nv_bfloat162(l0, l1);
            hw[q] = *(unsigned*)&hp2;
            lw[q] = *(unsigned*)&lp2;
        }
        *(uint4*)((__nv_bfloat16*)(sm + GA_HI(s)) + ar * LDA2 + ah) =
            make_uint4(hw[0], hw[1], hw[2], hw[3]);
        *(uint4*)((__nv_bfloat16*)(sm + GA_LO(s)) + ar * LDA2 + ah) =
            make_uint4(lw[0], lw[1], lw[2], lw[3]);
    };

    float xs[8], xs2[8];
    loadA_regs(xs, hh, sl, sc, g, 0, ah);
    copyB(0, 0);

    for (int c = 0; c < 9; ++c){
        const int s = c & 1;
        if (c < 8){
            loadA_regs(xs2, hh, sl, sc, g, c + 1, ah);
            copyB(c + 1, s ^ 1);
        }
        storeA(xs, s);
        if (c < 8) asm volatile("cp.async.wait_group 1;");
        else       asm volatile("cp.async.wait_group 0;");
        __syncthreads();

        const __nv_bfloat16* Ah = (const __nv_bfloat16*)(sm + GA_HI(s));
        const __nv_bfloat16* Al = (const __nv_bfloat16*)(sm + GA_LO(s));
        const __nv_bfloat16* Bh = (const __nv_bfloat16*)(sm + GB_HI(s));
        const __nv_bfloat16* Bl = (const __nv_bfloat16*)(sm + GB_LO(s));
#pragma unroll
        for (int kt = 0; kt < 2; ++kt){
            const int ks = kt * 16;
            wmma::fragment<wmma::matrix_a, 16, 16, 16, __nv_bfloat16, wmma::row_major> fa_hi[2], fa_lo[2];
#pragma unroll
            for (int i = 0; i < 2; ++i){
                wmma::load_matrix_sync(fa_hi[i], Ah + (wm*32 + i*16) * LDA2 + ks, LDA2);
                wmma::load_matrix_sync(fa_lo[i], Al + (wm*32 + i*16) * LDA2 + ks, LDA2);
            }
#pragma unroll
            for (int j = 0; j < 4; ++j){
                wmma::fragment<wmma::matrix_b, 16, 16, 16, __nv_bfloat16, wmma::row_major> fb_hi, fb_lo;
                wmma::load_matrix_sync(fb_hi, Bh + ks * LDB2 + wn*64 + j*16, LDB2);
                wmma::load_matrix_sync(fb_lo, Bl + ks * LDB2 + wn*64 + j*16, LDB2);
#pragma unroll
                for (int i = 0; i < 2; ++i){
                    wmma::mma_sync(acc[i][j], fa_hi[i], fb_hi, acc[i][j]);
                    wmma::mma_sync(acc[i][j], fa_hi[i], fb_lo, acc[i][j]);
                    wmma::mma_sync(acc[i][j], fa_lo[i], fb_hi, acc[i][j]);
                }
            }
        }
        __syncthreads();
#pragma unroll
        for (int q = 0; q < 8; ++q) xs[q] = xs2[q];
    }

#pragma unroll
    for (int i = 0; i < 2; ++i){
        const int row = m0 + wm * 32 + i * 16;
#pragma unroll
        for (int j = 0; j < 4; ++j){
            const int col = wn * 64 + j * 16;
            wmma::store_matrix_sync(
                g_feat + ((size_t)b * ND_ + row) * H_ + col,
                acc[i][j], H_, wmma::mem_row_major);
        }
    }
}

// ---------------- K6: gather-max (+bias) into output ----------------
__global__ void k_gather(float* __restrict__ out, const float* __restrict__ bias){
    const int wid = threadIdx.x >> 5, lane = threadIdx.x & 31;
    const int row = blockIdx.x * 8 + wid;
    float* op = out + (size_t)row * H_;
    const int c0 = lane * 4;
    const float4 z = make_float4(0.f, 0.f, 0.f, 0.f);
    const int deg = g_deg[row];
    if (!g_isup[row] || deg == 0){
        *(float4*)(op + c0) = z;
        *(float4*)(op + c0 + 128) = z;
        return;
    }
    const int off = g_off[row];
    const float NI = __int_as_float(0xff800000);
    float4 a = make_float4(NI, NI, NI, NI), bq = a;
    for (int e = 0; e < deg; ++e){
        const float* fp = g_feat + (size_t)g_src[off + e] * H_;
        float4 u = *(const float4*)(fp + c0);
        float4 v = *(const float4*)(fp + c0 + 128);
        a.x = fmaxf(a.x, u.x); a.y = fmaxf(a.y, u.y);
        a.z = fmaxf(a.z, u.z); a.w = fmaxf(a.w, u.w);
        bq.x = fmaxf(bq.x, v.x); bq.y = fmaxf(bq.y, v.y);
        bq.z = fmaxf(bq.z, v.z); bq.w = fmaxf(bq.w, v.w);
    }
    const float4 ba = *(const float4*)(bias + c0);
    const float4 bb = *(const float4*)(bias + c0 + 128);
    a.x += ba.x; a.y += ba.y; a.z += ba.z; a.w += ba.w;
    bq.x += bb.x; bq.y += bb.y; bq.z += bb.z; bq.w += bb.w;
    *(float4*)(op + c0) = a;
    *(float4*)(op + c0 + 128) = bq;
}

// ------------------------------- launch ------------------------------------
extern "C" void kernel_launch(void* const* d_in, const int* in_sizes, int n_in,
                              void* d_out, int out_size){
    const float* hh = (const float*)d_in[0];
    const float* sl = (const float*)d_in[1];
    const float* sc = (const float*)d_in[2];
    const float* W  = (const float*)d_in[3];
    const float* bb = (const float*)d_in[4];
    (void)in_sizes; (void)n_in;

    cudaFuncSetAttribute(k_gemm_tc, cudaFuncAttributeMaxDynamicSharedMemorySize, SMEM_G);

    // profile-slot rotation: knn now sits at launch index 3 (ncu -s5 -c1 window)
    k_wsplit<<<(KP_*H_ + 255)/256, 256>>>(W);                       // slot 0
    k_select<<<B_, 1024>>>(sc, (float*)d_out, (long long)out_size); // slot 1
    dim3 gg(ND_ / BM2, B_);
    k_gemm_tc<<<gg, GT_, SMEM_G>>>(hh, sl, sc);                     // slot 2
    dim3 gknn(ND_ / 512, B_);
    k_knn<<<gknn, 256>>>(sl);                                        // slot 3 (profiled)
    k_scan<<<B_, 1024>>>();                                          // slot 4
    k_fill<<<(B_*ND_*M_ + 255)/256, 256>>>();                        // slot 5
    k_gather<<<B_*N_/8, 256>>>((float*)d_out, bb);                   // slot 6
}

// round 8
// speedup vs baseline: 2.2807x; 1.2434x over previous
#include <cuda_runtime.h>
#include <cuda_bf16.h>
#include <mma.h>
#include <cstdint>

using namespace nvcuda;

#define B_  8
#define N_  8192
#define H_  256
#define KD_ 260            // H + 4
#define KP_ 288            // K padded to 9*32
#define NU_ 2048
#define ND_ 6144
#define M_  5
#define EPG (ND_*M_)       // edges per graph = 30720
#define KSL 2              // KNN candidate slices
#define NSL (NU_/KSL)      // 1024 candidates per slice
#define BM2 128            // GEMM M tile
#define GT_ 512            // GEMM threads
#define LDA2 40
#define LDB2 264
#define GA_HI(s) ((s)*10240)
#define GA_LO(s) (20480 + (s)*10240)
#define GB_HI(s) (40960 + (s)*16896)
#define GB_LO(s) (74752 + (s)*16896)
#define SMEM_G 108544

// ---------------- device scratch ----------------
__device__ int  g_up_idx[B_*NU_];
__device__ int  g_down_idx[B_*ND_];
__device__ int  g_dst[B_*ND_*M_];
__device__ unsigned char g_isup[B_*N_];
__device__ int  g_deg[B_*N_];
__device__ int  g_off[B_*N_];
__device__ int  g_cur[B_*N_];
__device__ int  g_src[B_*ND_*M_];
__device__ float g_feat[(size_t)B_*ND_*H_];
__device__ __nv_bfloat16 g_Whi[KP_*H_];
__device__ __nv_bfloat16 g_Wlo[KP_*H_];
__device__ float g_pd[(size_t)B_*ND_*KSL*M_];   // knn partial dists (sorted)
__device__ int   g_pi[(size_t)B_*ND_*KSL*M_];   // knn partial up-node ids

__device__ __forceinline__ unsigned enc_f(float f){
    unsigned u = __float_as_uint(f);
    return (u & 0x80000000u) ? ~u : (u | 0x80000000u);
}
__device__ __forceinline__ void cpa16(void* dst, const void* src){
    unsigned d = (unsigned)__cvta_generic_to_shared(dst);
    asm volatile("cp.async.cg.shared.global [%0], [%1], 16;" :: "r"(d), "l"(src));
}

// shuffle-based exclusive block scan (2 barriers)
__device__ __forceinline__ int block_scan_excl(int val, int* s_warp, int tid){
    const int lane = tid & 31, wid = tid >> 5;
    int inc = val;
#pragma unroll
    for (int o = 1; o < 32; o <<= 1){
        int v = __shfl_up_sync(0xFFFFFFFFu, inc, o);
        if (lane >= o) inc += v;
    }
    if (lane == 31) s_warp[wid] = inc;
    __syncthreads();
    if (wid == 0){
        int w = (lane < 32) ? s_warp[lane] : 0;
#pragma unroll
        for (int o = 1; o < 32; o <<= 1){
            int v = __shfl_up_sync(0xFFFFFFFFu, w, o);
            if (lane >= o) w += v;
        }
        s_warp[lane] = w;
    }
    __syncthreads();
    int base = (wid > 0) ? s_warp[wid - 1] : 0;
    return base + inc - val;
}

// ---------------- K0: W split into hi/lo bf16 ----------------
__global__ void k_wsplit(const float* __restrict__ W){
    const int idx = blockIdx.x * 256 + threadIdx.x;
    if (idx >= KP_ * H_) return;
    const int k = idx / H_, n = idx % H_;
    const float w = (k < KD_) ? W[k * H_ + n] : 0.0f;
    const __nv_bfloat16 hi = __float2bfloat16(w);
    const __nv_bfloat16 lo = __float2bfloat16(w - __bfloat162float(hi));
    g_Whi[idx] = hi;
    g_Wlo[idx] = lo;
}

// ---------------- K1: top-25% selection ----------------
__global__ void k_select(const float* __restrict__ scores,
                         float* __restrict__ d_out, long long out_size){
    __shared__ unsigned s_enc[N_];
    __shared__ int s_warp[32];
    __shared__ int s_hist[256];
    __shared__ int s_bcast[2];
    const int b = blockIdx.x, tid = threadIdx.x;

    for (int i = tid; i < N_; i += 1024) g_deg[b * N_ + i] = 0;

    const float* sc = scores + (long long)b * N_;
    for (int i = tid; i < N_; i += 1024) s_enc[i] = enc_f(sc[i]);
    __syncthreads();

    unsigned prefix = 0, known = 0;
    int k = NU_;
    for (int lvl = 3; lvl >= 0; --lvl){
        if (tid < 256) s_hist[tid] = 0;
        __syncthreads();
        const int sh = lvl * 8;
        for (int i = tid; i < N_; i += 1024){
            unsigned e = s_enc[i];
            if ((e & known) == prefix) atomicAdd(&s_hist[(e >> sh) & 255], 1);
        }
        __syncthreads();
        if (tid == 0){
            int kk = k, bin = 255;
            while (bin > 0 && kk > s_hist[bin]) { kk -= s_hist[bin]; --bin; }
            s_bcast[0] = bin; s_bcast[1] = kk;
        }
        __syncthreads();
        prefix |= ((unsigned)s_bcast[0]) << sh;
        known  |= 0xFFu << sh;
        k = s_bcast[1];
        __syncthreads();
    }
    const unsigned T = prefix;

    if (tid == 0) s_bcast[0] = 0;
    __syncthreads();
    {
        int loc = 0;
        for (int i = tid; i < N_; i += 1024) if (s_enc[i] > T) loc++;
        atomicAdd(&s_bcast[0], loc);
    }
    __syncthreads();
    const int need_eq = NU_ - s_bcast[0];
    __syncthreads();

    const int base = tid * 8;
    int eqc = 0;
#pragma unroll
    for (int e = 0; e < 8; ++e) eqc += (s_enc[base + e] == T);
    int eqbase = block_scan_excl(eqc, s_warp, tid);
    __syncthreads();

    unsigned mbits = 0; int upc = 0;
    {
        int ec = eqbase;
#pragma unroll
        for (int e = 0; e < 8; ++e){
            unsigned v = s_enc[base + e];
            bool msk;
            if (v > T) msk = true;
            else if (v == T) { msk = (ec < need_eq); ec++; }
            else msk = false;
            if (msk) { mbits |= (1u << e); upc++; }
        }
    }
    int upbase = block_scan_excl(upc, s_warp, tid);

    const long long BNH = (long long)B_ * N_ * H_;
    const bool wf = (out_size == BNH + (long long)B_ * N_);
    const bool wb = (out_size == BNH + ((long long)B_ * N_) / 4);
    int up = upbase;
#pragma unroll
    for (int e = 0; e < 8; ++e){
        const int i = base + e;
        const bool msk = (mbits >> e) & 1;
        if (msk) { g_up_idx[b * NU_ + up] = i; up++; }
        else       g_down_idx[b * ND_ + (i - up)] = i;
        g_isup[b * N_ + i] = msk ? 1 : 0;
        if (wf)      d_out[BNH + (long long)b * N_ + i] = msk ? 1.0f : 0.0f;
        else if (wb) ((unsigned char*)d_out)[BNH * 4 + (long long)b * N_ + i] = msk ? 1 : 0;
    }
}

// -------- K2a: KNN phase 1 — per-slice top-5 partials --------
struct Top5 { float d0,d1,d2,d3,d4; int i0,i1,i2,i3,i4; };
__device__ __forceinline__ void top5_init(Top5& t){
    const float INF = __int_as_float(0x7f800000);
    t.d0=t.d1=t.d2=t.d3=t.d4=INF; t.i0=t.i1=t.i2=t.i3=t.i4=0;
}
__device__ __forceinline__ void top5_ins(Top5& t, float d, int j){
    if (d < t.d4){
        if (d < t.d3){ t.d4=t.d3; t.i4=t.i3;
            if (d < t.d2){ t.d3=t.d2; t.i3=t.i2;
                if (d < t.d1){ t.d2=t.d1; t.i2=t.i1;
                    if (d < t.d0){ t.d1=t.d0; t.i1=t.i0; t.d0=d; t.i0=j; }
                    else        { t.d1=d;  t.i1=j; }
                } else { t.d2=d; t.i2=j; }
            } else { t.d3=d; t.i3=j; }
        } else { t.d4=d; t.i4=j; }
    }
}

__global__ void k_knn_part(const float* __restrict__ s_l){
    __shared__ float4 su[NSL];
    const int b  = blockIdx.y;
    const int sl = blockIdx.z;            // candidate slice
    const int tid = threadIdx.x;
    for (int j = tid; j < NSL; j += 256){
        int u = g_up_idx[b * NU_ + sl * NSL + j];
        long long p = ((long long)b * N_ + u) * 3;
        su[j] = make_float4(s_l[p], s_l[p+1], s_l[p+2], __int_as_float(b * N_ + u));
    }
    __syncthreads();

    const int dl = blockIdx.x * 256 + tid;
    const int dn = g_down_idx[b * ND_ + dl];
    long long p = ((long long)b * N_ + dn) * 3;
    const float x = s_l[p], y = s_l[p+1], z = s_l[p+2];

    Top5 t; top5_init(t);
    for (int j = 0; j < NSL; ++j){
        const float4 u = su[j];
        float dx = x-u.x, dy = y-u.y, dz = z-u.z;
        float d = dx*dx + dy*dy + dz*dz;
        top5_ins(t, d, j);
    }
    const size_t base = (((size_t)b * ND_ + dl) * KSL + sl) * M_;
    g_pd[base+0]=t.d0; g_pd[base+1]=t.d1; g_pd[base+2]=t.d2;
    g_pd[base+3]=t.d3; g_pd[base+4]=t.d4;
    g_pi[base+0]=__float_as_int(su[t.i0].w);
    g_pi[base+1]=__float_as_int(su[t.i1].w);
    g_pi[base+2]=__float_as_int(su[t.i2].w);
    g_pi[base+3]=__float_as_int(su[t.i3].w);
    g_pi[base+4]=__float_as_int(su[t.i4].w);
}

// -------- K2b: KNN phase 2 — merge 2 sorted 5-lists + degree count --------
// slice0 up-ids < slice1 up-ids; taking slice0 on d0<=d1 keeps
// lower-index-first tie semantics (== lax.top_k).
__global__ void k_knn_merge(){
    const int pt = blockIdx.x * 256 + threadIdx.x;
    if (pt >= B_ * ND_) return;
    const size_t b0 = (size_t)pt * KSL * M_;
    float d0[5], d1[5]; int i0[5], i1[5];
#pragma unroll
    for (int q = 0; q < 5; ++q){
        d0[q] = g_pd[b0 + q];      i0[q] = g_pi[b0 + q];
        d1[q] = g_pd[b0 + 5 + q];  i1[q] = g_pi[b0 + 5 + q];
    }
    int a = 0, c = 0;
    int* dst = g_dst + (size_t)pt * M_;
#pragma unroll
    for (int k = 0; k < 5; ++k){
        bool t0 = (a < 5) && (c >= 5 || d0[a] <= d1[c]);
        int e = t0 ? i0[a] : i1[c];
        if (t0) a++; else c++;
        dst[k] = e;
        atomicAdd(&g_deg[e], 1);
    }
}

// -------- K3: per-graph exclusive scan --------
__global__ void k_scan(){
    __shared__ int s_warp[32];
    const int b = blockIdx.x, tid = threadIdx.x;
    const int base = b * N_ + tid * 8;
    int d[8]; int s = 0;
#pragma unroll
    for (int i = 0; i < 8; ++i){ d[i] = g_deg[base + i]; s += d[i]; }
    int run = block_scan_excl(s, s_warp, tid) + b * EPG;
#pragma unroll
    for (int i = 0; i < 8; ++i){
        g_off[base + i] = run;
        g_cur[base + i] = run;
        run += d[i];
    }
}

// ---------------- K4: CSR fill ----------------
__global__ void k_fill(){
    const int e = blockIdx.x * 256 + threadIdx.x;
    if (e >= B_ * ND_ * M_) return;
    const int dst = g_dst[e];
    const int pos = atomicAdd(&g_cur[dst], 1);
    g_src[pos] = e / M_;
}

// -------- K5: pipelined WMMA bf16 hi/lo GEMM, BM=128 x BN=256, 512 thr ------
__device__ __forceinline__ void loadA_regs(float* xs, const float* __restrict__ hh,
                                           const float* __restrict__ sl,
                                           const float* __restrict__ sc,
                                           int g, int c, int ah){
    if (c < 8){
        const float4* hp = (const float4*)(hh + (size_t)g * H_ + c * 32 + ah);
        float4 f0 = hp[0], f1 = hp[1];
        xs[0]=f0.x; xs[1]=f0.y; xs[2]=f0.z; xs[3]=f0.w;
        xs[4]=f1.x; xs[5]=f1.y; xs[6]=f1.z; xs[7]=f1.w;
    } else {
#pragma unroll
        for (int q = 0; q < 8; ++q) xs[q] = 0.0f;
        if (ah == 0){
            xs[0] = sl[(size_t)g * 3];
            xs[1] = sl[(size_t)g * 3 + 1];
            xs[2] = sl[(size_t)g * 3 + 2];
            xs[3] = sc[g];
        }
    }
}

__global__ void __launch_bounds__(GT_, 1)
k_gemm_tc(const float* __restrict__ hh, const float* __restrict__ sl,
          const float* __restrict__ sc){
    extern __shared__ char sm[];
    __shared__ int s_g[BM2];

    const int b   = blockIdx.y;
    const int m0  = blockIdx.x * BM2;
    const int tid = threadIdx.x;
    const int w   = tid >> 5;
    const int wm  = w >> 2;
    const int wn  = w & 3;

    if (tid < BM2) s_g[tid] = b * N_ + g_down_idx[b * ND_ + m0 + tid];
    __syncthreads();

    const int ar = tid >> 2;
    const int ah = (tid & 3) * 8;
    const int g  = s_g[ar];

    wmma::fragment<wmma::accumulator, 16, 16, 16, float> acc[2][4];
#pragma unroll
    for (int i = 0; i < 2; ++i)
#pragma unroll
        for (int j = 0; j < 4; ++j) wmma::fill_fragment(acc[i][j], 0.0f);

    auto copyB = [&](int c, int s){
        const int k0 = c * 32;
        __nv_bfloat16* Bh = (__nv_bfloat16*)(sm + GB_HI(s));
        __nv_bfloat16* Bl = (__nv_bfloat16*)(sm + GB_LO(s));
#pragma unroll
        for (int q = 0; q < 2; ++q){
            const int i = tid + q * GT_;
            const int row = i >> 5;
            const int col = (i & 31) * 8;
            cpa16(Bh + row * LDB2 + col, g_Whi + (size_t)(k0 + row) * H_ + col);
            cpa16(Bl + row * LDB2 + col, g_Wlo + (size_t)(k0 + row) * H_ + col);
        }
        asm volatile("cp.async.commit_group;");
    };
    auto storeA = [&](const float* xs, int s){
        unsigned hw[4], lw[4];
#pragma unroll
        for (int q = 0; q < 4; ++q){
            __nv_bfloat16 h0 = __float2bfloat16(xs[2*q]);
            __nv_bfloat16 h1 = __float2bfloat16(xs[2*q+1]);
            __nv_bfloat16 l0 = __float2bfloat16(xs[2*q]   - __bfloat162float(h0));
            __nv_bfloat16 l1 = __float2bfloat16(xs[2*q+1] - __bfloat162float(h1));
            __nv_bfloat162 hp2 = __nv_bfloat162(h0, h1);
            __nv_bfloat162 lp2 = __nv_bfloat162(l0, l1);
            hw[q] = *(unsigned*)&hp2;
            lw[q] = *(unsigned*)&lp2;
        }
        *(uint4*)((__nv_bfloat16*)(sm + GA_HI(s)) + ar * LDA2 + ah) =
            make_uint4(hw[0], hw[1], hw[2], hw[3]);
        *(uint4*)((__nv_bfloat16*)(sm + GA_LO(s)) + ar * LDA2 + ah) =
            make_uint4(lw[0], lw[1], lw[2], lw[3]);
    };

    float xs[8], xs2[8];
    loadA_regs(xs, hh, sl, sc, g, 0, ah);
    copyB(0, 0);

    for (int c = 0; c < 9; ++c){
        const int s = c & 1;
        if (c < 8){
            loadA_regs(xs2, hh, sl, sc, g, c + 1, ah);
            copyB(c + 1, s ^ 1);
        }
        storeA(xs, s);
        if (c < 8) asm volatile("cp.async.wait_group 1;");
        else       asm volatile("cp.async.wait_group 0;");
        __syncthreads();

        const __nv_bfloat16* Ah = (const __nv_bfloat16*)(sm + GA_HI(s));
        const __nv_bfloat16* Al = (const __nv_bfloat16*)(sm + GA_LO(s));
        const __nv_bfloat16* Bh = (const __nv_bfloat16*)(sm + GB_HI(s));
        const __nv_bfloat16* Bl = (const __nv_bfloat16*)(sm + GB_LO(s));
#pragma unroll
        for (int kt = 0; kt < 2; ++kt){
            const int ks = kt * 16;
            wmma::fragment<wmma::matrix_a, 16, 16, 16, __nv_bfloat16, wmma::row_major> fa_hi[2], fa_lo[2];
#pragma unroll
            for (int i = 0; i < 2; ++i){
                wmma::load_matrix_sync(fa_hi[i], Ah + (wm*32 + i*16) * LDA2 + ks, LDA2);
                wmma::load_matrix_sync(fa_lo[i], Al + (wm*32 + i*16) * LDA2 + ks, LDA2);
            }
#pragma unroll
            for (int j = 0; j < 4; ++j){
                wmma::fragment<wmma::matrix_b, 16, 16, 16, __nv_bfloat16, wmma::row_major> fb_hi, fb_lo;
                wmma::load_matrix_sync(fb_hi, Bh + ks * LDB2 + wn*64 + j*16, LDB2);
                wmma::load_matrix_sync(fb_lo, Bl + ks * LDB2 + wn*64 + j*16, LDB2);
#pragma unroll
                for (int i = 0; i < 2; ++i){
                    wmma::mma_sync(acc[i][j], fa_hi[i], fb_hi, acc[i][j]);
                    wmma::mma_sync(acc[i][j], fa_hi[i], fb_lo, acc[i][j]);
                    wmma::mma_sync(acc[i][j], fa_lo[i], fb_hi, acc[i][j]);
                }
            }
        }
        __syncthreads();
#pragma unroll
        for (int q = 0; q < 8; ++q) xs[q] = xs2[q];
    }

#pragma unroll
    for (int i = 0; i < 2; ++i){
        const int row = m0 + wm * 32 + i * 16;
#pragma unroll
        for (int j = 0; j < 4; ++j){
            const int col = wn * 64 + j * 16;
            wmma::store_matrix_sync(
                g_feat + ((size_t)b * ND_ + row) * H_ + col,
                acc[i][j], H_, wmma::mem_row_major);
        }
    }
}

// ---------------- K6: gather-max (+bias) into output ----------------
__global__ void k_gather(float* __restrict__ out, const float* __restrict__ bias){
    const int wid = threadIdx.x >> 5, lane = threadIdx.x & 31;
    const int row = blockIdx.x * 8 + wid;
    float* op = out + (size_t)row * H_;
    const int c0 = lane * 4;
    const float4 z = make_float4(0.f, 0.f, 0.f, 0.f);
    const int deg = g_deg[row];
    if (!g_isup[row] || deg == 0){
        *(float4*)(op + c0) = z;
        *(float4*)(op + c0 + 128) = z;
        return;
    }
    const int off = g_off[row];
    const float NI = __int_as_float(0xff800000);
    float4 a = make_float4(NI, NI, NI, NI), bq = a;
    for (int e = 0; e < deg; ++e){
        const float* fp = g_feat + (size_t)g_src[off + e] * H_;
        float4 u = *(const float4*)(fp + c0);
        float4 v = *(const float4*)(fp + c0 + 128);
        a.x = fmaxf(a.x, u.x); a.y = fmaxf(a.y, u.y);
        a.z = fmaxf(a.z, u.z); a.w = fmaxf(a.w, u.w);
        bq.x = fmaxf(bq.x, v.x); bq.y = fmaxf(bq.y, v.y);
        bq.z = fmaxf(bq.z, v.z); bq.w = fmaxf(bq.w, v.w);
    }
    const float4 ba = *(const float4*)(bias + c0);
    const float4 bb = *(const float4*)(bias + c0 + 128);
    a.x += ba.x; a.y += ba.y; a.z += ba.z; a.w += ba.w;
    bq.x += bb.x; bq.y += bb.y; bq.z += bb.z; bq.w += bb.w;
    *(float4*)(op + c0) = a;
    *(float4*)(op + c0 + 128) = bq;
}

// ------------------------------- launch ------------------------------------
extern "C" void kernel_launch(void* const* d_in, const int* in_sizes, int n_in,
                              void* d_out, int out_size){
    const float* hh = (const float*)d_in[0];
    const float* sl = (const float*)d_in[1];
    const float* sc = (const float*)d_in[2];
    const float* W  = (const float*)d_in[3];
    const float* bb = (const float*)d_in[4];
    (void)in_sizes; (void)n_in;

    cudaFuncSetAttribute(k_gemm_tc, cudaFuncAttributeMaxDynamicSharedMemorySize, SMEM_G);

    k_wsplit<<<(KP_*H_ + 255)/256, 256>>>(W);                       // slot 0
    k_select<<<B_, 1024>>>(sc, (float*)d_out, (long long)out_size); // slot 1
    dim3 gknn(ND_ / 256, B_, KSL);
    k_knn_part<<<gknn, 256>>>(sl);                                   // slot 2
    dim3 gg(ND_ / BM2, B_);
    k_gemm_tc<<<gg, GT_, SMEM_G>>>(hh, sl, sc);                     // slot 3 (profiled)
    k_knn_merge<<<(B_*ND_ + 255)/256, 256>>>();                      // slot 4
    k_scan<<<B_, 1024>>>();                                          // slot 5
    k_fill<<<(B_*ND_*M_ + 255)/256, 256>>>();                        // slot 6
    k_gather<<<B_*N_/8, 256>>>((float*)d_out, bb);                   // slot 7
}